// round 4
// baseline (speedup 1.0000x reference)
#include <cuda_runtime.h>
#include <math.h>

#define B_     256
#define NG_    64
#define HEADS  6
#define CH     192
#define NTOK   216
#define HD     32
#define M_POS  1331
#define PDIM   12
#define MROWS  (B_*NTOK)   // 55296

#define KSTR   225         // Kt row stride (odd: conflict-free transposed STS; >=224 for j=6 pad)
#define VSTR   220         // Vt row stride (mult of 4 for float4)
#define POSPAD 1336        // posh padded for 16B alignment of pbuf

// ---------------- scratch ----------------
__device__ float g_q  [(size_t)B_*NTOK*CH];
__device__ float g_kv [(size_t)B_*NTOK*2*CH];
__device__ float g_att[(size_t)B_*NTOK*CH];
__device__ float g_pos[HEADS*M_POS];

// ---------------- tiny dynamic position-bias MLP ----------------
__device__ __forceinline__ void ln12(float* t, const float* g, const float* b) {
    float mu = 0.f;
    #pragma unroll
    for (int i = 0; i < PDIM; i++) mu += t[i];
    mu *= (1.f/PDIM);
    float v = 0.f;
    #pragma unroll
    for (int i = 0; i < PDIM; i++) { float d = t[i]-mu; v += d*d; }
    v *= (1.f/PDIM);
    float inv = rsqrtf(v + 1e-5f);
    #pragma unroll
    for (int i = 0; i < PDIM; i++) t[i] = (t[i]-mu)*inv*g[i] + b[i];
}

__global__ void pos_mlp_kernel(
    const float* __restrict__ ppw, const float* __restrict__ ppb,
    const float* __restrict__ g1,  const float* __restrict__ be1,
    const float* __restrict__ w1,  const float* __restrict__ b1,
    const float* __restrict__ g2,  const float* __restrict__ be2,
    const float* __restrict__ w2,  const float* __restrict__ b2,
    const float* __restrict__ g3,  const float* __restrict__ be3,
    const float* __restrict__ w3,  const float* __restrict__ b3)
{
    int m = blockIdx.x*blockDim.x + threadIdx.x;
    if (m >= M_POS) return;
    float c0 = (float)(m/121 - 5);
    float c1 = (float)((m/11)%11 - 5);
    float c2 = (float)(m%11 - 5);
    float t[PDIM], u[PDIM];
    #pragma unroll
    for (int i = 0; i < PDIM; i++)
        t[i] = ppw[i*3+0]*c0 + ppw[i*3+1]*c1 + ppw[i*3+2]*c2 + ppb[i];
    ln12(t, g1, be1);
    #pragma unroll
    for (int i = 0; i < PDIM; i++) {
        float acc = b1[i];
        #pragma unroll
        for (int j = 0; j < PDIM; j++) acc += w1[i*PDIM+j]*fmaxf(t[j],0.f);
        u[i] = acc;
    }
    ln12(u, g2, be2);
    #pragma unroll
    for (int i = 0; i < PDIM; i++) {
        float acc = b2[i];
        #pragma unroll
        for (int j = 0; j < PDIM; j++) acc += w2[i*PDIM+j]*fmaxf(u[j],0.f);
        t[i] = acc;
    }
    ln12(t, g3, be3);
    #pragma unroll
    for (int h = 0; h < HEADS; h++) {
        float acc = b3[h];
        #pragma unroll
        for (int j = 0; j < PDIM; j++) acc += w3[h*PDIM+j]*fmaxf(t[j],0.f);
        g_pos[h*M_POS + m] = acc;
    }
}

// ---------------- SGEMM: C[m][n] = sum_k A[m][k]*W[n][k] + bias[n] ----------------
// 128x64 CTA tile, 128 threads, 8x8 microtile, software-pipelined global loads.
__global__ __launch_bounds__(128)
void gemm_bias_kernel(const float* __restrict__ A, const float* __restrict__ W,
                      const float* __restrict__ bias, float* __restrict__ Cout,
                      int Mdim, int Ndim, int Kdim)
{
    __shared__ float As[16][132];
    __shared__ float Ws[16][68];
    int tid = threadIdx.x;
    int tx = tid & 7, ty = tid >> 3;       // tx: 8 col-groups, ty: 16 row-groups
    int m0 = blockIdx.y * 128, n0 = blockIdx.x * 64;

    int arow = tid >> 2;                   // 0..31
    int ak   = (tid & 3) * 4;              // 0,4,8,12
    const float* Aptr = A + (size_t)(m0 + arow)*Kdim + ak;
    int wrow = tid >> 1;                   // 0..63
    int wk   = (tid & 1) * 8;              // 0,8
    const float* Wptr = W + (size_t)(n0 + wrow)*Kdim + wk;

    float4 aR[4], wR[2];
    #pragma unroll
    for (int i = 0; i < 4; i++)
        aR[i] = *(const float4*)(Aptr + (size_t)(32*i)*Kdim);
    wR[0] = *(const float4*)(Wptr);
    wR[1] = *(const float4*)(Wptr + 4);

    float acc[8][8] = {};
    int nt = Kdim >> 4;

    for (int t = 0;;) {
        #pragma unroll
        for (int i = 0; i < 4; i++) {
            int r = arow + 32*i;
            As[ak+0][r] = aR[i].x; As[ak+1][r] = aR[i].y;
            As[ak+2][r] = aR[i].z; As[ak+3][r] = aR[i].w;
        }
        Ws[wk+0][wrow] = wR[0].x; Ws[wk+1][wrow] = wR[0].y;
        Ws[wk+2][wrow] = wR[0].z; Ws[wk+3][wrow] = wR[0].w;
        Ws[wk+4][wrow] = wR[1].x; Ws[wk+5][wrow] = wR[1].y;
        Ws[wk+6][wrow] = wR[1].z; Ws[wk+7][wrow] = wR[1].w;
        __syncthreads();
        t++;
        if (t < nt) {
            #pragma unroll
            for (int i = 0; i < 4; i++)
                aR[i] = *(const float4*)(Aptr + (size_t)(32*i)*Kdim + t*16);
            wR[0] = *(const float4*)(Wptr + t*16);
            wR[1] = *(const float4*)(Wptr + t*16 + 4);
        }
        #pragma unroll
        for (int k = 0; k < 16; k++) {
            float4 a0 = *(const float4*)&As[k][ty*8];
            float4 a1 = *(const float4*)&As[k][ty*8+4];
            float4 w0 = *(const float4*)&Ws[k][tx*8];
            float4 w1 = *(const float4*)&Ws[k][tx*8+4];
            float av[8] = {a0.x,a0.y,a0.z,a0.w,a1.x,a1.y,a1.z,a1.w};
            float wv[8] = {w0.x,w0.y,w0.z,w0.w,w1.x,w1.y,w1.z,w1.w};
            #pragma unroll
            for (int i = 0; i < 8; i++)
                #pragma unroll
                for (int j = 0; j < 8; j++)
                    acc[i][j] += av[i]*wv[j];
        }
        if (t >= nt) break;
        __syncthreads();
    }

    float4 b0 = *(const float4*)(bias + n0 + tx*8);
    float4 b1 = *(const float4*)(bias + n0 + tx*8 + 4);
    #pragma unroll
    for (int i = 0; i < 8; i++) {
        size_t off = (size_t)(m0 + ty*8 + i)*Ndim + n0 + tx*8;
        float4 o0, o1;
        o0.x = acc[i][0]+b0.x; o0.y = acc[i][1]+b0.y;
        o0.z = acc[i][2]+b0.z; o0.w = acc[i][3]+b0.w;
        o1.x = acc[i][4]+b1.x; o1.y = acc[i][5]+b1.y;
        o1.z = acc[i][6]+b1.z; o1.w = acc[i][7]+b1.w;
        *(float4*)&Cout[off]     = o0;
        *(float4*)&Cout[off + 4] = o1;
    }
}

// ---------------- fused attention ----------------
// one block per (b,h); 8 warps; each warp processes 8 query rows per group.
__global__ __launch_bounds__(256)
void attn_kernel(const float* __restrict__ mask)
{
    extern __shared__ float sm[];
    float* Kt   = sm;                 // [32][KSTR]  Kt[d*KSTR+m]
    float* Vt   = Kt + 32*KSTR;       // [32][VSTR]  Vt[d*VSTR+m]
    float* posh = Vt + 32*VSTR;       // [POSPAD]
    float* pbuf = posh + POSPAD;      // [8][4*216]

    int bh = blockIdx.x;
    int b  = bh / HEADS, h = bh % HEADS;
    int g  = b & (NG_-1);
    int tid = threadIdx.x;
    int w = tid >> 5, lane = tid & 31;

    const float* kvb = g_kv + (size_t)b*NTOK*(2*CH);
    for (int e = tid; e < NTOK*32; e += 256) {
        int m = e >> 5, d = e & 31;
        Kt[d*KSTR + m] = kvb[(size_t)m*(2*CH) + h*32 + d];
        Vt[d*VSTR + m] = kvb[(size_t)m*(2*CH) + CH + h*32 + d];
    }
    for (int e = tid; e < 32*(KSTR-NTOK); e += 256) {   // zero Kt pad (m=216..KSTR-1)
        int d = e / (KSTR-NTOK), p = e - d*(KSTR-NTOK);
        Kt[d*KSTR + NTOK + p] = 0.f;
    }
    for (int e = tid; e < M_POS; e += 256) posh[e] = g_pos[h*M_POS + e];
    __syncthreads();

    const float* maskb = mask + (size_t)g*NTOK*NTOK;
    const float scale    = 0.17677669529663687f;  // 32^-0.5
    const float invscale = 5.656854249492381f;    // 32^0.5
    float* pw = pbuf + w*(4*NTOK);

    int mid[7];
    #pragma unroll
    for (int j = 0; j < 7; j++) {
        int m = lane + 32*j;
        mid[j] = (m/36)*121 + ((m/6)%6)*11 + (m%6);
    }

    for (int grp = w; grp < NTOK/8; grp += 8) {
        int n0 = grp*8;
        float qv[8];
        #pragma unroll
        for (int r = 0; r < 8; r++)
            qv[r] = g_q[((size_t)b*NTOK + n0 + r)*CH + h*32 + lane];

        // init accumulators with (pos_bias + mask)/scale
        float s[8][7];
        #pragma unroll
        for (int r = 0; r < 8; r++) {
            int n = n0 + r;
            int nid = (n/36)*121 + ((n/6)%6)*11 + (n%6);
            const float* mrow = maskb + (size_t)n*NTOK;
            #pragma unroll
            for (int j = 0; j < 7; j++) {
                int m = lane + 32*j;
                s[r][j] = (m < NTOK)
                    ? (posh[nid - mid[j] + 665] + mrow[m]) * invscale
                    : 0.f;
            }
        }

        // QK^T: 8-row register blocking, K reused 8x
        #pragma unroll
        for (int d = 0; d < 32; d++) {
            float kreg[7];
            const float* Kd = Kt + d*KSTR + lane;
            #pragma unroll
            for (int j = 0; j < 7; j++) kreg[j] = Kd[32*j];
            #pragma unroll
            for (int r = 0; r < 8; r++) {
                float qd = __shfl_sync(0xffffffffu, qv[r], d);
                #pragma unroll
                for (int j = 0; j < 7; j++) s[r][j] += qd * kreg[j];
            }
        }

        // softmax per row; exp values stay in s[][]
        float inv_[8];
        #pragma unroll
        for (int r = 0; r < 8; r++) {
            float lmax = -1e30f;
            #pragma unroll
            for (int j = 0; j < 7; j++) {
                float f = ((lane + 32*j) < NTOK) ? s[r][j]*scale : -1e30f;
                s[r][j] = f;
                lmax = fmaxf(lmax, f);
            }
            #pragma unroll
            for (int o = 16; o > 0; o >>= 1)
                lmax = fmaxf(lmax, __shfl_xor_sync(0xffffffffu, lmax, o));
            float lsum = 0.f;
            #pragma unroll
            for (int j = 0; j < 7; j++) {
                float e = __expf(s[r][j] - lmax);
                s[r][j] = e;
                lsum += e;
            }
            #pragma unroll
            for (int o = 16; o > 0; o >>= 1)
                lsum += __shfl_xor_sync(0xffffffffu, lsum, o);
            inv_[r] = 1.f / lsum;
        }

        // PV in two 4-row passes through the per-warp p buffer
        float accs[8];
        const float* vrow = Vt + lane*VSTR;
        #pragma unroll
        for (int pass = 0; pass < 2; pass++) {
            __syncwarp();
            #pragma unroll
            for (int rr = 0; rr < 4; rr++) {
                int r = pass*4 + rr;
                #pragma unroll
                for (int j = 0; j < 7; j++) {
                    int m = lane + 32*j;
                    if (m < NTOK) pw[rr*NTOK + m] = s[r][j];
                }
            }
            __syncwarp();
            float a0 = 0.f, a1 = 0.f, a2 = 0.f, a3 = 0.f;
            #pragma unroll 2
            for (int mq = 0; mq < NTOK/4; mq++) {
                float4 v  = *(const float4*)(vrow + 4*mq);
                float4 p0 = *(const float4*)(pw + 0*NTOK + 4*mq);
                float4 p1 = *(const float4*)(pw + 1*NTOK + 4*mq);
                float4 p2 = *(const float4*)(pw + 2*NTOK + 4*mq);
                float4 p3 = *(const float4*)(pw + 3*NTOK + 4*mq);
                a0 += p0.x*v.x + p0.y*v.y + p0.z*v.z + p0.w*v.w;
                a1 += p1.x*v.x + p1.y*v.y + p1.z*v.z + p1.w*v.w;
                a2 += p2.x*v.x + p2.y*v.y + p2.z*v.z + p2.w*v.w;
                a3 += p3.x*v.x + p3.y*v.y + p3.z*v.z + p3.w*v.w;
            }
            accs[pass*4+0] = a0; accs[pass*4+1] = a1;
            accs[pass*4+2] = a2; accs[pass*4+3] = a3;
        }
        #pragma unroll
        for (int r = 0; r < 8; r++)
            g_att[((size_t)b*NTOK + n0 + r)*CH + h*32 + lane] = accs[r] * inv_[r];
        __syncwarp();
    }
}

// ---------------- launch ----------------
extern "C" void kernel_launch(void* const* d_in, const int* in_sizes, int n_in,
                              void* d_out, int out_size)
{
    const float* x     = (const float*)d_in[0];
    const float* y     = (const float*)d_in[1];
    const float* mask  = (const float*)d_in[2];
    const float* Wqkv  = (const float*)d_in[3];
    const float* bqkv  = (const float*)d_in[4];
    const float* Wproj = (const float*)d_in[5];
    const float* bproj = (const float*)d_in[6];
    const float* ppw   = (const float*)d_in[7];
    const float* ppb   = (const float*)d_in[8];
    const float* g1    = (const float*)d_in[9];
    const float* be1   = (const float*)d_in[10];
    const float* w1    = (const float*)d_in[11];
    const float* b1    = (const float*)d_in[12];
    const float* g2    = (const float*)d_in[13];
    const float* be2   = (const float*)d_in[14];
    const float* w2    = (const float*)d_in[15];
    const float* b2    = (const float*)d_in[16];
    const float* g3    = (const float*)d_in[17];
    const float* be3   = (const float*)d_in[18];
    const float* w3    = (const float*)d_in[19];
    const float* b3    = (const float*)d_in[20];
    float* out = (float*)d_out;

    float *qp, *kvp, *attp;
    cudaGetSymbolAddress((void**)&qp,  g_q);
    cudaGetSymbolAddress((void**)&kvp, g_kv);
    cudaGetSymbolAddress((void**)&attp, g_att);

    pos_mlp_kernel<<<(M_POS+255)/256, 256>>>(ppw, ppb, g1, be1, w1, b1,
                                             g2, be2, w2, b2, g3, be3, w3, b3);
    {
        dim3 grid(CH/64, MROWS/128);
        gemm_bias_kernel<<<grid, 128>>>(x, Wqkv, bqkv, qp, MROWS, CH, CH);
    }
    {
        dim3 grid((2*CH)/64, MROWS/128);
        gemm_bias_kernel<<<grid, 128>>>(y, Wqkv + (size_t)CH*CH, bqkv + CH,
                                        kvp, MROWS, 2*CH, CH);
    }
    {
        size_t smem = (size_t)(32*KSTR + 32*VSTR + POSPAD + 8*4*NTOK) * sizeof(float);
        cudaFuncSetAttribute(attn_kernel, cudaFuncAttributeMaxDynamicSharedMemorySize, (int)smem);
        attn_kernel<<<B_*HEADS, 256, smem>>>(mask);
    }
    {
        dim3 grid(CH/64, MROWS/128);
        gemm_bias_kernel<<<grid, 128>>>(attp, Wproj, bproj, out, MROWS, CH, CH);
    }
}

// round 5
// speedup vs baseline: 2.1699x; 2.1699x over previous
#include <cuda_runtime.h>
#include <math.h>
#include <stdint.h>

#define B_     256
#define NG_    64
#define HEADS  6
#define CH     192
#define NTOK   216
#define HD     32
#define M_POS  1331
#define PDIM   12
#define MROWS  (B_*NTOK)   // 55296

#define KSTR   225         // Kt row stride (odd: conflict-free transposed STS; >=224 for j=6 pad)
#define VSTR   220         // Vt row stride (mult of 4 for float4)
#define POSPAD 1336        // posh padded for 16B alignment of pbuf

// ---------------- scratch ----------------
__device__ float g_q  [(size_t)B_*NTOK*CH];
__device__ float g_kv [(size_t)B_*NTOK*2*CH];
__device__ float g_att[(size_t)B_*NTOK*CH];
__device__ float g_pos[HEADS*M_POS];

// ---------------- tiny dynamic position-bias MLP ----------------
__device__ __forceinline__ void ln12(float* t, const float* g, const float* b) {
    float mu = 0.f;
    #pragma unroll
    for (int i = 0; i < PDIM; i++) mu += t[i];
    mu *= (1.f/PDIM);
    float v = 0.f;
    #pragma unroll
    for (int i = 0; i < PDIM; i++) { float d = t[i]-mu; v += d*d; }
    v *= (1.f/PDIM);
    float inv = rsqrtf(v + 1e-5f);
    #pragma unroll
    for (int i = 0; i < PDIM; i++) t[i] = (t[i]-mu)*inv*g[i] + b[i];
}

__global__ void pos_mlp_kernel(
    const float* __restrict__ ppw, const float* __restrict__ ppb,
    const float* __restrict__ g1,  const float* __restrict__ be1,
    const float* __restrict__ w1,  const float* __restrict__ b1,
    const float* __restrict__ g2,  const float* __restrict__ be2,
    const float* __restrict__ w2,  const float* __restrict__ b2,
    const float* __restrict__ g3,  const float* __restrict__ be3,
    const float* __restrict__ w3,  const float* __restrict__ b3)
{
    int m = blockIdx.x*blockDim.x + threadIdx.x;
    if (m >= M_POS) return;
    float c0 = (float)(m/121 - 5);
    float c1 = (float)((m/11)%11 - 5);
    float c2 = (float)(m%11 - 5);
    float t[PDIM], u[PDIM];
    #pragma unroll
    for (int i = 0; i < PDIM; i++)
        t[i] = ppw[i*3+0]*c0 + ppw[i*3+1]*c1 + ppw[i*3+2]*c2 + ppb[i];
    ln12(t, g1, be1);
    #pragma unroll
    for (int i = 0; i < PDIM; i++) {
        float acc = b1[i];
        #pragma unroll
        for (int j = 0; j < PDIM; j++) acc += w1[i*PDIM+j]*fmaxf(t[j],0.f);
        u[i] = acc;
    }
    ln12(u, g2, be2);
    #pragma unroll
    for (int i = 0; i < PDIM; i++) {
        float acc = b2[i];
        #pragma unroll
        for (int j = 0; j < PDIM; j++) acc += w2[i*PDIM+j]*fmaxf(u[j],0.f);
        t[i] = acc;
    }
    ln12(t, g3, be3);
    #pragma unroll
    for (int h = 0; h < HEADS; h++) {
        float acc = b3[h];
        #pragma unroll
        for (int j = 0; j < PDIM; j++) acc += w3[h*PDIM+j]*fmaxf(t[j],0.f);
        g_pos[h*M_POS + m] = acc;
    }
}

// ---------------- TF32 tensor-core GEMM ----------------
// C[m][n] = sum_k A[m][k]*W[n][k] + bias[n]
// 128x64 CTA tile, 256 threads (8 warps, 4x2), warp tile 32x32, mma.m16n8k8 tf32.
#define GK 16          // k per SMEM stage
#define ASTR 20        // SMEM row stride (conflict-free for frag pattern)

__device__ __forceinline__ uint32_t f2tf(float f) {
    uint32_t r;
    asm("cvt.rna.tf32.f32 %0, %1;" : "=r"(r) : "f"(f));
    return r;
}

__global__ __launch_bounds__(256)
void gemm_tf32_kernel(const float* __restrict__ A, const float* __restrict__ W,
                      const float* __restrict__ bias, float* __restrict__ Cout,
                      int Mdim, int Ndim, int Kdim)
{
    __shared__ uint32_t As[128*ASTR];
    __shared__ uint32_t Ws[64*ASTR];

    int tid  = threadIdx.x;
    int w    = tid >> 5, lane = tid & 31;
    int grp  = lane >> 2, tig = lane & 3;
    int wm   = (w >> 1) * 32;           // warp m offset (4 warps along m)
    int wn   = (w & 1) * 32;            // warp n offset (2 warps along n)
    int m0   = blockIdx.y * 128, n0 = blockIdx.x * 64;

    // global load mapping
    int arow = tid >> 2;                 // 0..63 (and +64)
    int ak   = (tid & 3) * 4;            // 0,4,8,12
    const float* Aptr = A + (size_t)(m0 + arow)*Kdim + ak;
    const float* Wptr = W + (size_t)(n0 + arow)*Kdim + ak;   // arow<64 valid for W

    float4 aR0 = *(const float4*)Aptr;
    float4 aR1 = *(const float4*)(Aptr + (size_t)64*Kdim);
    float4 wR  = *(const float4*)Wptr;

    float acc[2][4][4];
    #pragma unroll
    for (int i = 0; i < 2; i++)
        #pragma unroll
        for (int j = 0; j < 4; j++)
            #pragma unroll
            for (int c = 0; c < 4; c++) acc[i][j][c] = 0.f;

    int nstage = Kdim / GK;

    for (int st = 0;;) {
        // store stage to SMEM (tf32-converted), 16B-aligned uint4 stores
        {
            uint4 v0 = make_uint4(f2tf(aR0.x), f2tf(aR0.y), f2tf(aR0.z), f2tf(aR0.w));
            uint4 v1 = make_uint4(f2tf(aR1.x), f2tf(aR1.y), f2tf(aR1.z), f2tf(aR1.w));
            uint4 v2 = make_uint4(f2tf(wR.x),  f2tf(wR.y),  f2tf(wR.z),  f2tf(wR.w));
            *(uint4*)&As[(arow     )*ASTR + ak] = v0;
            *(uint4*)&As[(arow + 64)*ASTR + ak] = v1;
            *(uint4*)&Ws[(arow     )*ASTR + ak] = v2;
        }
        __syncthreads();
        st++;
        if (st < nstage) {
            aR0 = *(const float4*)(Aptr + st*GK);
            aR1 = *(const float4*)(Aptr + (size_t)64*Kdim + st*GK);
            wR  = *(const float4*)(Wptr + st*GK);
        }
        // compute: 2 k-steps of 8
        #pragma unroll
        for (int ks = 0; ks < 2; ks++) {
            int kb = ks*8;
            uint32_t af[2][4], bf[4][2];
            #pragma unroll
            for (int mf = 0; mf < 2; mf++) {
                int r = wm + mf*16 + grp;
                af[mf][0] = As[(r    )*ASTR + kb + tig];
                af[mf][1] = As[(r + 8)*ASTR + kb + tig];
                af[mf][2] = As[(r    )*ASTR + kb + tig + 4];
                af[mf][3] = As[(r + 8)*ASTR + kb + tig + 4];
            }
            #pragma unroll
            for (int nf = 0; nf < 4; nf++) {
                int n = wn + nf*8 + grp;
                bf[nf][0] = Ws[n*ASTR + kb + tig];
                bf[nf][1] = Ws[n*ASTR + kb + tig + 4];
            }
            #pragma unroll
            for (int mf = 0; mf < 2; mf++)
                #pragma unroll
                for (int nf = 0; nf < 4; nf++) {
                    asm volatile(
                        "mma.sync.aligned.m16n8k8.row.col.f32.tf32.tf32.f32 "
                        "{%0,%1,%2,%3}, {%4,%5,%6,%7}, {%8,%9}, {%0,%1,%2,%3};"
                        : "+f"(acc[mf][nf][0]), "+f"(acc[mf][nf][1]),
                          "+f"(acc[mf][nf][2]), "+f"(acc[mf][nf][3])
                        : "r"(af[mf][0]), "r"(af[mf][1]), "r"(af[mf][2]), "r"(af[mf][3]),
                          "r"(bf[nf][0]), "r"(bf[nf][1]));
                }
        }
        if (st >= nstage) break;
        __syncthreads();
    }

    // epilogue: c0,c1 -> (row grp, cols 2tig,2tig+1); c2,c3 -> row grp+8
    #pragma unroll
    for (int mf = 0; mf < 2; mf++) {
        #pragma unroll
        for (int nf = 0; nf < 4; nf++) {
            int col = n0 + wn + nf*8 + 2*tig;
            float bx = bias[col], by = bias[col+1];
            int r0 = m0 + wm + mf*16 + grp;
            float2 o0 = make_float2(acc[mf][nf][0] + bx, acc[mf][nf][1] + by);
            float2 o1 = make_float2(acc[mf][nf][2] + bx, acc[mf][nf][3] + by);
            *(float2*)&Cout[(size_t)r0*Ndim + col]       = o0;
            *(float2*)&Cout[(size_t)(r0+8)*Ndim + col]   = o1;
        }
    }
}

// ---------------- fused attention (R2 version: 4-row blocking) ----------------
__global__ __launch_bounds__(256)
void attn_kernel(const float* __restrict__ mask)
{
    extern __shared__ float sm[];
    float* Kt   = sm;                 // [32][KSTR]  Kt[d*KSTR+m]
    float* Vt   = Kt + 32*KSTR;       // [32][VSTR]  Vt[d*VSTR+m]
    float* posh = Vt + 32*VSTR;       // [POSPAD]
    float* pbuf = posh + POSPAD;      // [8][4*216]

    int bh = blockIdx.x;
    int b  = bh / HEADS, h = bh % HEADS;
    int g  = b & (NG_-1);
    int tid = threadIdx.x;
    int w = tid >> 5, lane = tid & 31;

    const float* kvb = g_kv + (size_t)b*NTOK*(2*CH);
    for (int e = tid; e < NTOK*32; e += 256) {
        int m = e >> 5, d = e & 31;
        Kt[d*KSTR + m] = kvb[(size_t)m*(2*CH) + h*32 + d];
        Vt[d*VSTR + m] = kvb[(size_t)m*(2*CH) + CH + h*32 + d];
    }
    for (int e = tid; e < 32*(KSTR-NTOK); e += 256) {   // zero Kt pad
        int d = e / (KSTR-NTOK), p = e - d*(KSTR-NTOK);
        Kt[d*KSTR + NTOK + p] = 0.f;
    }
    for (int e = tid; e < M_POS; e += 256) posh[e] = g_pos[h*M_POS + e];
    __syncthreads();

    const float* maskb = mask + (size_t)g*NTOK*NTOK;
    const float scale    = 0.17677669529663687f;  // 32^-0.5
    const float invscale = 5.656854249492381f;    // 32^0.5
    float* pw = pbuf + w*(4*NTOK);

    int mid[7];
    #pragma unroll
    for (int j = 0; j < 7; j++) {
        int m = lane + 32*j;
        mid[j] = (m/36)*121 + ((m/6)%6)*11 + (m%6);
    }

    for (int grp = w; grp < NTOK/4; grp += 8) {
        int n0 = grp*4;
        float qv[4];
        #pragma unroll
        for (int r = 0; r < 4; r++)
            qv[r] = g_q[((size_t)b*NTOK + n0 + r)*CH + h*32 + lane];

        float s[4][7];
        #pragma unroll
        for (int r = 0; r < 4; r++) {
            int n = n0 + r;
            int nid = (n/36)*121 + ((n/6)%6)*11 + (n%6);
            #pragma unroll
            for (int j = 0; j < 7; j++) {
                int m = lane + 32*j;
                s[r][j] = (m < NTOK)
                    ? (posh[nid - mid[j] + 665] + maskb[(size_t)n*NTOK + m]) * invscale
                    : 0.f;
            }
        }

        #pragma unroll
        for (int d = 0; d < 32; d++) {
            float kreg[7];
            const float* Kd = Kt + d*KSTR + lane;
            #pragma unroll
            for (int j = 0; j < 7; j++) kreg[j] = Kd[32*j];
            #pragma unroll
            for (int r = 0; r < 4; r++) {
                float qd = __shfl_sync(0xffffffffu, qv[r], d);
                #pragma unroll
                for (int j = 0; j < 7; j++) s[r][j] += qd * kreg[j];
            }
        }

        float inv_[4];
        #pragma unroll
        for (int r = 0; r < 4; r++) {
            float lmax = -1e30f;
            #pragma unroll
            for (int j = 0; j < 7; j++) {
                float f = ((lane + 32*j) < NTOK) ? s[r][j]*scale : -1e30f;
                s[r][j] = f;
                lmax = fmaxf(lmax, f);
            }
            #pragma unroll
            for (int o = 16; o > 0; o >>= 1)
                lmax = fmaxf(lmax, __shfl_xor_sync(0xffffffffu, lmax, o));
            float lsum = 0.f;
            #pragma unroll
            for (int j = 0; j < 7; j++) {
                float e = __expf(s[r][j] - lmax);
                int m = lane + 32*j;
                if (m < NTOK) pw[r*NTOK + m] = e;
                lsum += e;
            }
            #pragma unroll
            for (int o = 16; o > 0; o >>= 1)
                lsum += __shfl_xor_sync(0xffffffffu, lsum, o);
            inv_[r] = 1.f / lsum;
        }
        __syncwarp();

        float acc0 = 0.f, acc1 = 0.f, acc2 = 0.f, acc3 = 0.f;
        const float* vrow = Vt + lane*VSTR;
        #pragma unroll 2
        for (int mq = 0; mq < NTOK/4; mq++) {
            float4 v  = *(const float4*)(vrow + 4*mq);
            float4 p0 = *(const float4*)(pw + 0*NTOK + 4*mq);
            float4 p1 = *(const float4*)(pw + 1*NTOK + 4*mq);
            float4 p2 = *(const float4*)(pw + 2*NTOK + 4*mq);
            float4 p3 = *(const float4*)(pw + 3*NTOK + 4*mq);
            acc0 += p0.x*v.x + p0.y*v.y + p0.z*v.z + p0.w*v.w;
            acc1 += p1.x*v.x + p1.y*v.y + p1.z*v.z + p1.w*v.w;
            acc2 += p2.x*v.x + p2.y*v.y + p2.z*v.z + p2.w*v.w;
            acc3 += p3.x*v.x + p3.y*v.y + p3.z*v.z + p3.w*v.w;
        }
        float accs[4] = {acc0, acc1, acc2, acc3};
        #pragma unroll
        for (int r = 0; r < 4; r++)
            g_att[((size_t)b*NTOK + n0 + r)*CH + h*32 + lane] = accs[r] * inv_[r];
        __syncwarp();
    }
}

// ---------------- launch ----------------
extern "C" void kernel_launch(void* const* d_in, const int* in_sizes, int n_in,
                              void* d_out, int out_size)
{
    const float* x     = (const float*)d_in[0];
    const float* y     = (const float*)d_in[1];
    const float* mask  = (const float*)d_in[2];
    const float* Wqkv  = (const float*)d_in[3];
    const float* bqkv  = (const float*)d_in[4];
    const float* Wproj = (const float*)d_in[5];
    const float* bproj = (const float*)d_in[6];
    const float* ppw   = (const float*)d_in[7];
    const float* ppb   = (const float*)d_in[8];
    const float* g1    = (const float*)d_in[9];
    const float* be1   = (const float*)d_in[10];
    const float* w1    = (const float*)d_in[11];
    const float* b1    = (const float*)d_in[12];
    const float* g2    = (const float*)d_in[13];
    const float* be2   = (const float*)d_in[14];
    const float* w2    = (const float*)d_in[15];
    const float* b2    = (const float*)d_in[16];
    const float* g3    = (const float*)d_in[17];
    const float* be3   = (const float*)d_in[18];
    const float* w3    = (const float*)d_in[19];
    const float* b3    = (const float*)d_in[20];
    float* out = (float*)d_out;

    float *qp, *kvp, *attp;
    cudaGetSymbolAddress((void**)&qp,  g_q);
    cudaGetSymbolAddress((void**)&kvp, g_kv);
    cudaGetSymbolAddress((void**)&attp, g_att);

    pos_mlp_kernel<<<(M_POS+255)/256, 256>>>(ppw, ppb, g1, be1, w1, b1,
                                             g2, be2, w2, b2, g3, be3, w3, b3);
    {
        dim3 grid(CH/64, MROWS/128);
        gemm_tf32_kernel<<<grid, 256>>>(x, Wqkv, bqkv, qp, MROWS, CH, CH);
    }
    {
        dim3 grid((2*CH)/64, MROWS/128);
        gemm_tf32_kernel<<<grid, 256>>>(y, Wqkv + (size_t)CH*CH, bqkv + CH,
                                        kvp, MROWS, 2*CH, CH);
    }
    {
        size_t smem = (size_t)(32*KSTR + 32*VSTR + POSPAD + 8*4*NTOK) * sizeof(float);
        cudaFuncSetAttribute(attn_kernel, cudaFuncAttributeMaxDynamicSharedMemorySize, (int)smem);
        attn_kernel<<<B_*HEADS, 256, smem>>>(mask);
    }
    {
        dim3 grid(CH/64, MROWS/128);
        gemm_tf32_kernel<<<grid, 256>>>(attp, Wproj, bproj, out, MROWS, CH, CH);
    }
}

// round 6
// speedup vs baseline: 3.1245x; 1.4399x over previous
#include <cuda_runtime.h>
#include <math.h>
#include <stdint.h>

#define B_     256
#define NG_    64
#define HEADS  6
#define CH     192
#define NTOK   216
#define HD     32
#define M_POS  1331
#define PDIM   12
#define MROWS  (B_*NTOK)   // 55296

// attention tiling
#define NP      224        // padded token count (14 m16 tiles / 28 n8 tiles)
#define KS_STR  36         // K smem row stride (words): bank = 4*grp+tig, conflict-free
#define VT_STR  228        // V^T smem row stride: 228%32=4 -> conflict-free B-frags
#define NT      28         // n8 tiles
#define MT      14         // m16 strips

// ---------------- scratch ----------------
__device__ float g_q  [(size_t)B_*NTOK*CH];
__device__ float g_kv [(size_t)B_*NTOK*2*CH];
__device__ float g_att[(size_t)B_*NTOK*CH];
__device__ float g_pos[HEADS*M_POS];

__device__ __forceinline__ uint32_t f2tf(float f) {
    uint32_t r;
    asm("cvt.rna.tf32.f32 %0, %1;" : "=r"(r) : "f"(f));
    return r;
}

// ---------------- tiny dynamic position-bias MLP ----------------
__device__ __forceinline__ void ln12(float* t, const float* g, const float* b) {
    float mu = 0.f;
    #pragma unroll
    for (int i = 0; i < PDIM; i++) mu += t[i];
    mu *= (1.f/PDIM);
    float v = 0.f;
    #pragma unroll
    for (int i = 0; i < PDIM; i++) { float d = t[i]-mu; v += d*d; }
    v *= (1.f/PDIM);
    float inv = rsqrtf(v + 1e-5f);
    #pragma unroll
    for (int i = 0; i < PDIM; i++) t[i] = (t[i]-mu)*inv*g[i] + b[i];
}

__global__ void pos_mlp_kernel(
    const float* __restrict__ ppw, const float* __restrict__ ppb,
    const float* __restrict__ g1,  const float* __restrict__ be1,
    const float* __restrict__ w1,  const float* __restrict__ b1,
    const float* __restrict__ g2,  const float* __restrict__ be2,
    const float* __restrict__ w2,  const float* __restrict__ b2,
    const float* __restrict__ g3,  const float* __restrict__ be3,
    const float* __restrict__ w3,  const float* __restrict__ b3)
{
    int m = blockIdx.x*blockDim.x + threadIdx.x;
    if (m >= M_POS) return;
    float c0 = (float)(m/121 - 5);
    float c1 = (float)((m/11)%11 - 5);
    float c2 = (float)(m%11 - 5);
    float t[PDIM], u[PDIM];
    #pragma unroll
    for (int i = 0; i < PDIM; i++)
        t[i] = ppw[i*3+0]*c0 + ppw[i*3+1]*c1 + ppw[i*3+2]*c2 + ppb[i];
    ln12(t, g1, be1);
    #pragma unroll
    for (int i = 0; i < PDIM; i++) {
        float acc = b1[i];
        #pragma unroll
        for (int j = 0; j < PDIM; j++) acc += w1[i*PDIM+j]*fmaxf(t[j],0.f);
        u[i] = acc;
    }
    ln12(u, g2, be2);
    #pragma unroll
    for (int i = 0; i < PDIM; i++) {
        float acc = b2[i];
        #pragma unroll
        for (int j = 0; j < PDIM; j++) acc += w2[i*PDIM+j]*fmaxf(u[j],0.f);
        t[i] = acc;
    }
    ln12(t, g3, be3);
    #pragma unroll
    for (int h = 0; h < HEADS; h++) {
        float acc = b3[h];
        #pragma unroll
        for (int j = 0; j < PDIM; j++) acc += w3[h*PDIM+j]*fmaxf(t[j],0.f);
        g_pos[h*M_POS + m] = acc;
    }
}

// ---------------- TF32 tensor-core GEMM (validated R4) ----------------
#define GK 16
#define ASTR 20

__global__ __launch_bounds__(256)
void gemm_tf32_kernel(const float* __restrict__ A, const float* __restrict__ W,
                      const float* __restrict__ bias, float* __restrict__ Cout,
                      int Mdim, int Ndim, int Kdim)
{
    __shared__ uint32_t As[128*ASTR];
    __shared__ uint32_t Ws[64*ASTR];

    int tid  = threadIdx.x;
    int w    = tid >> 5, lane = tid & 31;
    int grp  = lane >> 2, tig = lane & 3;
    int wm   = (w >> 1) * 32;
    int wn   = (w & 1) * 32;
    int m0   = blockIdx.y * 128, n0 = blockIdx.x * 64;

    int arow = tid >> 2;
    int ak   = (tid & 3) * 4;
    const float* Aptr = A + (size_t)(m0 + arow)*Kdim + ak;
    const float* Wptr = W + (size_t)(n0 + arow)*Kdim + ak;

    float4 aR0 = *(const float4*)Aptr;
    float4 aR1 = *(const float4*)(Aptr + (size_t)64*Kdim);
    float4 wR  = *(const float4*)Wptr;

    float acc[2][4][4];
    #pragma unroll
    for (int i = 0; i < 2; i++)
        #pragma unroll
        for (int j = 0; j < 4; j++)
            #pragma unroll
            for (int c = 0; c < 4; c++) acc[i][j][c] = 0.f;

    int nstage = Kdim / GK;

    for (int st = 0;;) {
        {
            uint4 v0 = make_uint4(f2tf(aR0.x), f2tf(aR0.y), f2tf(aR0.z), f2tf(aR0.w));
            uint4 v1 = make_uint4(f2tf(aR1.x), f2tf(aR1.y), f2tf(aR1.z), f2tf(aR1.w));
            uint4 v2 = make_uint4(f2tf(wR.x),  f2tf(wR.y),  f2tf(wR.z),  f2tf(wR.w));
            *(uint4*)&As[(arow     )*ASTR + ak] = v0;
            *(uint4*)&As[(arow + 64)*ASTR + ak] = v1;
            *(uint4*)&Ws[(arow     )*ASTR + ak] = v2;
        }
        __syncthreads();
        st++;
        if (st < nstage) {
            aR0 = *(const float4*)(Aptr + st*GK);
            aR1 = *(const float4*)(Aptr + (size_t)64*Kdim + st*GK);
            wR  = *(const float4*)(Wptr + st*GK);
        }
        #pragma unroll
        for (int ks = 0; ks < 2; ks++) {
            int kb = ks*8;
            uint32_t af[2][4], bf[4][2];
            #pragma unroll
            for (int mf = 0; mf < 2; mf++) {
                int r = wm + mf*16 + grp;
                af[mf][0] = As[(r    )*ASTR + kb + tig];
                af[mf][1] = As[(r + 8)*ASTR + kb + tig];
                af[mf][2] = As[(r    )*ASTR + kb + tig + 4];
                af[mf][3] = As[(r + 8)*ASTR + kb + tig + 4];
            }
            #pragma unroll
            for (int nf = 0; nf < 4; nf++) {
                int n = wn + nf*8 + grp;
                bf[nf][0] = Ws[n*ASTR + kb + tig];
                bf[nf][1] = Ws[n*ASTR + kb + tig + 4];
            }
            #pragma unroll
            for (int mf = 0; mf < 2; mf++)
                #pragma unroll
                for (int nf = 0; nf < 4; nf++) {
                    asm volatile(
                        "mma.sync.aligned.m16n8k8.row.col.f32.tf32.tf32.f32 "
                        "{%0,%1,%2,%3}, {%4,%5,%6,%7}, {%8,%9}, {%0,%1,%2,%3};"
                        : "+f"(acc[mf][nf][0]), "+f"(acc[mf][nf][1]),
                          "+f"(acc[mf][nf][2]), "+f"(acc[mf][nf][3])
                        : "r"(af[mf][0]), "r"(af[mf][1]), "r"(af[mf][2]), "r"(af[mf][3]),
                          "r"(bf[nf][0]), "r"(bf[nf][1]));
                }
        }
        if (st >= nstage) break;
        __syncthreads();
    }

    #pragma unroll
    for (int mf = 0; mf < 2; mf++) {
        #pragma unroll
        for (int nf = 0; nf < 4; nf++) {
            int col = n0 + wn + nf*8 + 2*tig;
            float bx = bias[col], by = bias[col+1];
            int r0 = m0 + wm + mf*16 + grp;
            float2 o0 = make_float2(acc[mf][nf][0] + bx, acc[mf][nf][1] + by);
            float2 o1 = make_float2(acc[mf][nf][2] + bx, acc[mf][nf][3] + by);
            *(float2*)&Cout[(size_t)r0*Ndim + col]       = o0;
            *(float2*)&Cout[(size_t)(r0+8)*Ndim + col]   = o1;
        }
    }
}

// ---------------- tensor-core fused attention ----------------
__device__ __forceinline__ int pid3(int n) {
    return (n/36)*121 + ((n/6)%6)*11 + (n%6);
}

__global__ __launch_bounds__(256, 1)
void attn_tc_kernel(const float* __restrict__ mask)
{
    extern __shared__ uint32_t smu[];
    uint32_t* Ks  = smu;                    // [224][36] tf32
    uint32_t* Vt  = Ks + NP*KS_STR;         // [32][228] tf32 (V^T)
    float*    posh = (float*)(Vt + 32*VT_STR); // [1331]

    int bh = blockIdx.x;
    int b  = bh / HEADS, h = bh % HEADS;
    int g  = b & (NG_-1);
    int tid = threadIdx.x;
    int w = tid >> 5, lane = tid & 31;
    int grp = lane >> 2, tig = lane & 3;

    const float* kvb = g_kv + (size_t)b*NTOK*(2*CH);
    for (int e = tid; e < NP*32; e += 256) {
        int m = e >> 5, d = e & 31;
        float kf = (m < NTOK) ? kvb[(size_t)m*(2*CH) + h*32 + d]      : 0.f;
        float vf = (m < NTOK) ? kvb[(size_t)m*(2*CH) + CH + h*32 + d] : 0.f;
        Ks[m*KS_STR + d]  = f2tf(kf);
        Vt[d*VT_STR + m]  = f2tf(vf);
    }
    for (int e = tid; e < M_POS; e += 256) posh[e] = g_pos[h*M_POS + e];
    __syncthreads();

    const float* maskb = mask + (size_t)g*NTOK*NTOK;
    const float* qb = g_q + (size_t)b*NTOK*CH + h*32;
    float* ob = g_att + (size_t)b*NTOK*CH + h*32;
    const float scale = 0.17677669529663687f;  // 32^-0.5

    for (int strip = w; strip < MT; strip += 8) {
        int n0 = strip*16;
        int ra = n0 + grp, rb = ra + 8;
        int ra_c = min(ra, NTOK-1), rb_c = min(rb, NTOK-1);

        // Q A-frags (4 k8-steps)
        uint32_t aq[4][4];
        const float* qa = qb + (size_t)ra_c*CH;
        const float* qB = qb + (size_t)rb_c*CH;
        #pragma unroll
        for (int ks = 0; ks < 4; ks++) {
            aq[ks][0] = f2tf(qa[ks*8 + tig]);
            aq[ks][1] = f2tf(qB[ks*8 + tig]);
            aq[ks][2] = f2tf(qa[ks*8 + tig + 4]);
            aq[ks][3] = f2tf(qB[ks*8 + tig + 4]);
        }

        // S = Q K^T
        float s[NT][4];
        #pragma unroll
        for (int nt = 0; nt < NT; nt++)
            #pragma unroll
            for (int c = 0; c < 4; c++) s[nt][c] = 0.f;

        #pragma unroll
        for (int nt = 0; nt < NT; nt++) {
            int mrow = nt*8 + grp;
            #pragma unroll
            for (int ks = 0; ks < 4; ks++) {
                uint32_t b0 = Ks[mrow*KS_STR + ks*8 + tig];
                uint32_t b1 = Ks[mrow*KS_STR + ks*8 + tig + 4];
                asm volatile(
                    "mma.sync.aligned.m16n8k8.row.col.f32.tf32.tf32.f32 "
                    "{%0,%1,%2,%3}, {%4,%5,%6,%7}, {%8,%9}, {%0,%1,%2,%3};"
                    : "+f"(s[nt][0]), "+f"(s[nt][1]), "+f"(s[nt][2]), "+f"(s[nt][3])
                    : "r"(aq[ks][0]), "r"(aq[ks][1]), "r"(aq[ks][2]), "r"(aq[ks][3]),
                      "r"(b0), "r"(b1));
            }
        }

        // scale + pos bias + mask, row max
        int nida = pid3(ra_c), nidb = pid3(rb_c);
        float mxa = -1e30f, mxb = -1e30f;
        #pragma unroll
        for (int nt = 0; nt < NT; nt++) {
            if (nt*8 + 7 < NTOK) {   // compile-time per tile (only nt=27 invalid)
                int m0 = nt*8 + 2*tig;
                int mid0 = pid3(m0), mid1 = pid3(m0+1);
                float2 ma = *(const float2*)(maskb + (size_t)ra_c*NTOK + m0);
                float2 mb = *(const float2*)(maskb + (size_t)rb_c*NTOK + m0);
                s[nt][0] = s[nt][0]*scale + posh[nida - mid0 + 665] + ma.x;
                s[nt][1] = s[nt][1]*scale + posh[nida - mid1 + 665] + ma.y;
                s[nt][2] = s[nt][2]*scale + posh[nidb - mid0 + 665] + mb.x;
                s[nt][3] = s[nt][3]*scale + posh[nidb - mid1 + 665] + mb.y;
                mxa = fmaxf(mxa, fmaxf(s[nt][0], s[nt][1]));
                mxb = fmaxf(mxb, fmaxf(s[nt][2], s[nt][3]));
            } else {
                s[nt][0] = -1e30f; s[nt][1] = -1e30f;
                s[nt][2] = -1e30f; s[nt][3] = -1e30f;
            }
        }
        mxa = fmaxf(mxa, __shfl_xor_sync(0xffffffffu, mxa, 1));
        mxa = fmaxf(mxa, __shfl_xor_sync(0xffffffffu, mxa, 2));
        mxb = fmaxf(mxb, __shfl_xor_sync(0xffffffffu, mxb, 1));
        mxb = fmaxf(mxb, __shfl_xor_sync(0xffffffffu, mxb, 2));

        float sa = 0.f, sb = 0.f;
        #pragma unroll
        for (int nt = 0; nt < NT; nt++) {
            s[nt][0] = __expf(s[nt][0] - mxa);
            s[nt][1] = __expf(s[nt][1] - mxa);
            s[nt][2] = __expf(s[nt][2] - mxb);
            s[nt][3] = __expf(s[nt][3] - mxb);
            sa += s[nt][0] + s[nt][1];
            sb += s[nt][2] + s[nt][3];
        }
        sa += __shfl_xor_sync(0xffffffffu, sa, 1);
        sa += __shfl_xor_sync(0xffffffffu, sa, 2);
        sb += __shfl_xor_sync(0xffffffffu, sb, 1);
        sb += __shfl_xor_sync(0xffffffffu, sb, 2);
        float inva = 1.f / sa, invb = 1.f / sb;

        // O = P V  (P C-frag -> A-frag via shfl.idx, V^T B-frags from SMEM)
        float o[4][4];
        #pragma unroll
        for (int dt = 0; dt < 4; dt++)
            #pragma unroll
            for (int c = 0; c < 4; c++) o[dt][c] = 0.f;

        int src0 = (lane & ~3) | (tig >> 1);
        int src1 = src0 + 2;
        bool odd = (tig & 1);

        #pragma unroll
        for (int kt = 0; kt < NT; kt++) {
            float v00 = __shfl_sync(0xffffffffu, s[kt][0], src0);
            float v01 = __shfl_sync(0xffffffffu, s[kt][1], src0);
            float v02 = __shfl_sync(0xffffffffu, s[kt][2], src0);
            float v03 = __shfl_sync(0xffffffffu, s[kt][3], src0);
            float v10 = __shfl_sync(0xffffffffu, s[kt][0], src1);
            float v11 = __shfl_sync(0xffffffffu, s[kt][1], src1);
            float v12 = __shfl_sync(0xffffffffu, s[kt][2], src1);
            float v13 = __shfl_sync(0xffffffffu, s[kt][3], src1);
            uint32_t pa0 = f2tf(odd ? v01 : v00);   // P[grp][tig]
            uint32_t pa1 = f2tf(odd ? v03 : v02);   // P[grp+8][tig]
            uint32_t pa2 = f2tf(odd ? v11 : v10);   // P[grp][tig+4]
            uint32_t pa3 = f2tf(odd ? v13 : v12);   // P[grp+8][tig+4]
            #pragma unroll
            for (int dt = 0; dt < 4; dt++) {
                uint32_t b0 = Vt[(dt*8 + grp)*VT_STR + kt*8 + tig];
                uint32_t b1 = Vt[(dt*8 + grp)*VT_STR + kt*8 + tig + 4];
                asm volatile(
                    "mma.sync.aligned.m16n8k8.row.col.f32.tf32.tf32.f32 "
                    "{%0,%1,%2,%3}, {%4,%5,%6,%7}, {%8,%9}, {%0,%1,%2,%3};"
                    : "+f"(o[dt][0]), "+f"(o[dt][1]), "+f"(o[dt][2]), "+f"(o[dt][3])
                    : "r"(pa0), "r"(pa1), "r"(pa2), "r"(pa3),
                      "r"(b0), "r"(b1));
            }
        }

        // epilogue
        #pragma unroll
        for (int dt = 0; dt < 4; dt++) {
            int d = dt*8 + 2*tig;
            *(float2*)&ob[(size_t)ra*CH + d] =
                make_float2(o[dt][0]*inva, o[dt][1]*inva);
            if (rb < NTOK)
                *(float2*)&ob[(size_t)rb*CH + d] =
                    make_float2(o[dt][2]*invb, o[dt][3]*invb);
        }
    }
}

// ---------------- launch ----------------
extern "C" void kernel_launch(void* const* d_in, const int* in_sizes, int n_in,
                              void* d_out, int out_size)
{
    const float* x     = (const float*)d_in[0];
    const float* y     = (const float*)d_in[1];
    const float* mask  = (const float*)d_in[2];
    const float* Wqkv  = (const float*)d_in[3];
    const float* bqkv  = (const float*)d_in[4];
    const float* Wproj = (const float*)d_in[5];
    const float* bproj = (const float*)d_in[6];
    const float* ppw   = (const float*)d_in[7];
    const float* ppb   = (const float*)d_in[8];
    const float* g1    = (const float*)d_in[9];
    const float* be1   = (const float*)d_in[10];
    const float* w1    = (const float*)d_in[11];
    const float* b1    = (const float*)d_in[12];
    const float* g2    = (const float*)d_in[13];
    const float* be2   = (const float*)d_in[14];
    const float* w2    = (const float*)d_in[15];
    const float* b2    = (const float*)d_in[16];
    const float* g3    = (const float*)d_in[17];
    const float* be3   = (const float*)d_in[18];
    const float* w3    = (const float*)d_in[19];
    const float* b3    = (const float*)d_in[20];
    float* out = (float*)d_out;

    float *qp, *kvp, *attp;
    cudaGetSymbolAddress((void**)&qp,  g_q);
    cudaGetSymbolAddress((void**)&kvp, g_kv);
    cudaGetSymbolAddress((void**)&attp, g_att);

    pos_mlp_kernel<<<(M_POS+255)/256, 256>>>(ppw, ppb, g1, be1, w1, b1,
                                             g2, be2, w2, b2, g3, be3, w3, b3);
    {
        dim3 grid(CH/64, MROWS/128);
        gemm_tf32_kernel<<<grid, 256>>>(x, Wqkv, bqkv, qp, MROWS, CH, CH);
    }
    {
        dim3 grid((2*CH)/64, MROWS/128);
        gemm_tf32_kernel<<<grid, 256>>>(y, Wqkv + (size_t)CH*CH, bqkv + CH,
                                        kvp, MROWS, 2*CH, CH);
    }
    {
        size_t smem = (size_t)(NP*KS_STR + 32*VT_STR + M_POS + 1) * 4;
        cudaFuncSetAttribute(attn_tc_kernel, cudaFuncAttributeMaxDynamicSharedMemorySize, (int)smem);
        attn_tc_kernel<<<B_*HEADS, 256, smem>>>(mask);
    }
    {
        dim3 grid(CH/64, MROWS/128);
        gemm_tf32_kernel<<<grid, 256>>>(attp, Wproj, bproj, out, MROWS, CH, CH);
    }
}

// round 8
// speedup vs baseline: 3.2524x; 1.0409x over previous
#include <cuda_runtime.h>
#include <math.h>
#include <stdint.h>

#define B_     256
#define NG_    64
#define HEADS  6
#define CH     192
#define NTOK   216
#define HD     32
#define M_POS  1331
#define PDIM   12
#define MROWS  (B_*NTOK)   // 55296

// attention tiling
#define KS_STR  36         // K smem row stride (words): conflict-free B-frags
#define VT_STR  228        // V^T smem row stride: 228%32=4 -> conflict-free B-frags
#define NT      27         // n8 key tiles (216 = 27*8 exactly)
#define MT      14         // m16 query strips (224 padded rows)

// ---------------- scratch ----------------
__device__ float g_q  [(size_t)B_*NTOK*CH];
__device__ float g_kv [(size_t)B_*NTOK*2*CH];
__device__ float g_att[(size_t)B_*NTOK*CH];
__device__ float g_pos[HEADS*M_POS];

__device__ __forceinline__ uint32_t f2tf(float f) {
    uint32_t r;
    asm("cvt.rna.tf32.f32 %0, %1;" : "=r"(r) : "f"(f));
    return r;
}

// ---------------- tiny dynamic position-bias MLP ----------------
__device__ __forceinline__ void ln12(float* t, const float* g, const float* b) {
    float mu = 0.f;
    #pragma unroll
    for (int i = 0; i < PDIM; i++) mu += t[i];
    mu *= (1.f/PDIM);
    float v = 0.f;
    #pragma unroll
    for (int i = 0; i < PDIM; i++) { float d = t[i]-mu; v += d*d; }
    v *= (1.f/PDIM);
    float inv = rsqrtf(v + 1e-5f);
    #pragma unroll
    for (int i = 0; i < PDIM; i++) t[i] = (t[i]-mu)*inv*g[i] + b[i];
}

__global__ void pos_mlp_kernel(
    const float* __restrict__ ppw, const float* __restrict__ ppb,
    const float* __restrict__ g1,  const float* __restrict__ be1,
    const float* __restrict__ w1,  const float* __restrict__ b1,
    const float* __restrict__ g2,  const float* __restrict__ be2,
    const float* __restrict__ w2,  const float* __restrict__ b2,
    const float* __restrict__ g3,  const float* __restrict__ be3,
    const float* __restrict__ w3,  const float* __restrict__ b3)
{
    int m = blockIdx.x*blockDim.x + threadIdx.x;
    if (m >= M_POS) return;
    float c0 = (float)(m/121 - 5);
    float c1 = (float)((m/11)%11 - 5);
    float c2 = (float)(m%11 - 5);
    float t[PDIM], u[PDIM];
    #pragma unroll
    for (int i = 0; i < PDIM; i++)
        t[i] = ppw[i*3+0]*c0 + ppw[i*3+1]*c1 + ppw[i*3+2]*c2 + ppb[i];
    ln12(t, g1, be1);
    #pragma unroll
    for (int i = 0; i < PDIM; i++) {
        float acc = b1[i];
        #pragma unroll
        for (int j = 0; j < PDIM; j++) acc += w1[i*PDIM+j]*fmaxf(t[j],0.f);
        u[i] = acc;
    }
    ln12(u, g2, be2);
    #pragma unroll
    for (int i = 0; i < PDIM; i++) {
        float acc = b2[i];
        #pragma unroll
        for (int j = 0; j < PDIM; j++) acc += w2[i*PDIM+j]*fmaxf(u[j],0.f);
        t[i] = acc;
    }
    ln12(t, g3, be3);
    #pragma unroll
    for (int h = 0; h < HEADS; h++) {
        float acc = b3[h];
        #pragma unroll
        for (int j = 0; j < PDIM; j++) acc += w3[h*PDIM+j]*fmaxf(t[j],0.f);
        g_pos[h*M_POS + m] = acc;
    }
}

// ---------------- TF32 tensor-core GEMM (validated R4) ----------------
#define GK 16
#define ASTR 20

__global__ __launch_bounds__(256)
void gemm_tf32_kernel(const float* __restrict__ A, const float* __restrict__ W,
                      const float* __restrict__ bias, float* __restrict__ Cout,
                      int Mdim, int Ndim, int Kdim)
{
    __shared__ uint32_t As[128*ASTR];
    __shared__ uint32_t Ws[64*ASTR];

    int tid  = threadIdx.x;
    int w    = tid >> 5, lane = tid & 31;
    int grp  = lane >> 2, tig = lane & 3;
    int wm   = (w >> 1) * 32;
    int wn   = (w & 1) * 32;
    int m0   = blockIdx.y * 128, n0 = blockIdx.x * 64;

    int arow = tid >> 2;
    int ak   = (tid & 3) * 4;
    const float* Aptr = A + (size_t)(m0 + arow)*Kdim + ak;
    const float* Wptr = W + (size_t)(n0 + arow)*Kdim + ak;

    float4 aR0 = *(const float4*)Aptr;
    float4 aR1 = *(const float4*)(Aptr + (size_t)64*Kdim);
    float4 wR  = *(const float4*)Wptr;

    float acc[2][4][4];
    #pragma unroll
    for (int i = 0; i < 2; i++)
        #pragma unroll
        for (int j = 0; j < 4; j++)
            #pragma unroll
            for (int c = 0; c < 4; c++) acc[i][j][c] = 0.f;

    int nstage = Kdim / GK;

    for (int st = 0;;) {
        {
            uint4 v0 = make_uint4(f2tf(aR0.x), f2tf(aR0.y), f2tf(aR0.z), f2tf(aR0.w));
            uint4 v1 = make_uint4(f2tf(aR1.x), f2tf(aR1.y), f2tf(aR1.z), f2tf(aR1.w));
            uint4 v2 = make_uint4(f2tf(wR.x),  f2tf(wR.y),  f2tf(wR.z),  f2tf(wR.w));
            *(uint4*)&As[(arow     )*ASTR + ak] = v0;
            *(uint4*)&As[(arow + 64)*ASTR + ak] = v1;
            *(uint4*)&Ws[(arow     )*ASTR + ak] = v2;
        }
        __syncthreads();
        st++;
        if (st < nstage) {
            aR0 = *(const float4*)(Aptr + st*GK);
            aR1 = *(const float4*)(Aptr + (size_t)64*Kdim + st*GK);
            wR  = *(const float4*)(Wptr + st*GK);
        }
        #pragma unroll
        for (int ks = 0; ks < 2; ks++) {
            int kb = ks*8;
            uint32_t af[2][4], bf[4][2];
            #pragma unroll
            for (int mf = 0; mf < 2; mf++) {
                int r = wm + mf*16 + grp;
                af[mf][0] = As[(r    )*ASTR + kb + tig];
                af[mf][1] = As[(r + 8)*ASTR + kb + tig];
                af[mf][2] = As[(r    )*ASTR + kb + tig + 4];
                af[mf][3] = As[(r + 8)*ASTR + kb + tig + 4];
            }
            #pragma unroll
            for (int nf = 0; nf < 4; nf++) {
                int n = wn + nf*8 + grp;
                bf[nf][0] = Ws[n*ASTR + kb + tig];
                bf[nf][1] = Ws[n*ASTR + kb + tig + 4];
            }
            #pragma unroll
            for (int mf = 0; mf < 2; mf++)
                #pragma unroll
                for (int nf = 0; nf < 4; nf++) {
                    asm volatile(
                        "mma.sync.aligned.m16n8k8.row.col.f32.tf32.tf32.f32 "
                        "{%0,%1,%2,%3}, {%4,%5,%6,%7}, {%8,%9}, {%0,%1,%2,%3};"
                        : "+f"(acc[mf][nf][0]), "+f"(acc[mf][nf][1]),
                          "+f"(acc[mf][nf][2]), "+f"(acc[mf][nf][3])
                        : "r"(af[mf][0]), "r"(af[mf][1]), "r"(af[mf][2]), "r"(af[mf][3]),
                          "r"(bf[nf][0]), "r"(bf[nf][1]));
                }
        }
        if (st >= nstage) break;
        __syncthreads();
    }

    #pragma unroll
    for (int mf = 0; mf < 2; mf++) {
        #pragma unroll
        for (int nf = 0; nf < 4; nf++) {
            int col = n0 + wn + nf*8 + 2*tig;
            float bx = bias[col], by = bias[col+1];
            int r0 = m0 + wm + mf*16 + grp;
            float2 o0 = make_float2(acc[mf][nf][0] + bx, acc[mf][nf][1] + by);
            float2 o1 = make_float2(acc[mf][nf][2] + bx, acc[mf][nf][3] + by);
            *(float2*)&Cout[(size_t)r0*Ndim + col]       = o0;
            *(float2*)&Cout[(size_t)(r0+8)*Ndim + col]   = o1;
        }
    }
}

// ---------------- tensor-core fused attention (online, max-free softmax) ----------------
__global__ __launch_bounds__(256)
void attn_tc_kernel(const float* __restrict__ mask)
{
    extern __shared__ uint32_t smu[];
    uint32_t* Ks   = smu;                         // [216][36] tf32
    uint32_t* Vt   = Ks + NTOK*KS_STR;            // [32][228] tf32 (V^T)
    float*    posh = (float*)(Vt + 32*VT_STR);    // [1331]
    int*      midv = (int*)(posh + M_POS);        // [216] pid3 LUT

    int bh = blockIdx.x;
    int b  = bh / HEADS, h = bh % HEADS;
    int g  = b & (NG_-1);
    int tid = threadIdx.x;
    int w = tid >> 5, lane = tid & 31;
    int grp = lane >> 2, tig = lane & 3;

    const float* kvb = g_kv + (size_t)b*NTOK*(2*CH);
    for (int e = tid; e < NTOK*32; e += 256) {
        int m = e >> 5, d = e & 31;
        Ks[m*KS_STR + d] = f2tf(kvb[(size_t)m*(2*CH) + h*32 + d]);
        Vt[d*VT_STR + m] = f2tf(kvb[(size_t)m*(2*CH) + CH + h*32 + d]);
    }
    for (int e = tid; e < M_POS; e += 256) posh[e] = g_pos[h*M_POS + e];
    for (int e = tid; e < NTOK; e += 256)
        midv[e] = (e/36)*121 + ((e/6)%6)*11 + (e%6);
    __syncthreads();

    const float* maskb = mask + (size_t)g*NTOK*NTOK;
    const float* qb = g_q + (size_t)b*NTOK*CH + h*32;
    float* ob = g_att + (size_t)b*NTOK*CH + h*32;
    const float scale = 0.17677669529663687f;  // 32^-0.5

    int src0 = (lane & ~3) | (tig >> 1);
    int src1 = src0 + 2;
    bool odd = (tig & 1);

    for (int strip = w; strip < MT; strip += 8) {
        int n0 = strip*16;
        int ra = n0 + grp, rb = ra + 8;
        int ra_c = min(ra, NTOK-1), rb_c = min(rb, NTOK-1);

        // Q A-frags (4 k8-steps)
        uint32_t aq[4][4];
        const float* qa = qb + (size_t)ra_c*CH;
        const float* qB = qb + (size_t)rb_c*CH;
        #pragma unroll
        for (int ks = 0; ks < 4; ks++) {
            aq[ks][0] = f2tf(qa[ks*8 + tig]);
            aq[ks][1] = f2tf(qB[ks*8 + tig]);
            aq[ks][2] = f2tf(qa[ks*8 + tig + 4]);
            aq[ks][3] = f2tf(qB[ks*8 + tig + 4]);
        }

        int nida = midv[ra_c], nidb = midv[rb_c];
        const float* mra = maskb + (size_t)ra_c*NTOK;
        const float* mrb = maskb + (size_t)rb_c*NTOK;

        float o[4][4];
        #pragma unroll
        for (int dt = 0; dt < 4; dt++)
            #pragma unroll
            for (int c = 0; c < 4; c++) o[dt][c] = 0.f;
        float sa = 0.f, sb = 0.f;

        #pragma unroll 3
        for (int kt = 0; kt < NT; kt++) {
            // S tile = Q K^T
            float s0 = 0.f, s1 = 0.f, s2 = 0.f, s3 = 0.f;
            int mrow = kt*8 + grp;
            #pragma unroll
            for (int ks = 0; ks < 4; ks++) {
                uint32_t b0 = Ks[mrow*KS_STR + ks*8 + tig];
                uint32_t b1 = Ks[mrow*KS_STR + ks*8 + tig + 4];
                asm volatile(
                    "mma.sync.aligned.m16n8k8.row.col.f32.tf32.tf32.f32 "
                    "{%0,%1,%2,%3}, {%4,%5,%6,%7}, {%8,%9}, {%0,%1,%2,%3};"
                    : "+f"(s0), "+f"(s1), "+f"(s2), "+f"(s3)
                    : "r"(aq[ks][0]), "r"(aq[ks][1]), "r"(aq[ks][2]), "r"(aq[ks][3]),
                      "r"(b0), "r"(b1));
            }

            // bias + mask + exp (no max subtraction: scores are O(1); -1e6 underflows to 0)
            int m0 = kt*8 + 2*tig;
            int mid0 = midv[m0], mid1 = midv[m0+1];
            float2 ma = *(const float2*)(mra + m0);
            float2 mb = *(const float2*)(mrb + m0);
            s0 = __expf(s0*scale + posh[nida - mid0 + 665] + ma.x);
            s1 = __expf(s1*scale + posh[nida - mid1 + 665] + ma.y);
            s2 = __expf(s2*scale + posh[nidb - mid0 + 665] + mb.x);
            s3 = __expf(s3*scale + posh[nidb - mid1 + 665] + mb.y);
            sa += s0 + s1;
            sb += s2 + s3;

            // C-frag -> A-frag via shfl.idx
            float v00 = __shfl_sync(0xffffffffu, s0, src0);
            float v01 = __shfl_sync(0xffffffffu, s1, src0);
            float v02 = __shfl_sync(0xffffffffu, s2, src0);
            float v03 = __shfl_sync(0xffffffffu, s3, src0);
            float v10 = __shfl_sync(0xffffffffu, s0, src1);
            float v11 = __shfl_sync(0xffffffffu, s1, src1);
            float v12 = __shfl_sync(0xffffffffu, s2, src1);
            float v13 = __shfl_sync(0xffffffffu, s3, src1);
            uint32_t pa0 = f2tf(odd ? v01 : v00);   // P[grp][tig]
            uint32_t pa1 = f2tf(odd ? v03 : v02);   // P[grp+8][tig]
            uint32_t pa2 = f2tf(odd ? v11 : v10);   // P[grp][tig+4]
            uint32_t pa3 = f2tf(odd ? v13 : v12);   // P[grp+8][tig+4]

            // O += P V
            #pragma unroll
            for (int dt = 0; dt < 4; dt++) {
                uint32_t b0 = Vt[(dt*8 + grp)*VT_STR + kt*8 + tig];
                uint32_t b1 = Vt[(dt*8 + grp)*VT_STR + kt*8 + tig + 4];
                asm volatile(
                    "mma.sync.aligned.m16n8k8.row.col.f32.tf32.tf32.f32 "
                    "{%0,%1,%2,%3}, {%4,%5,%6,%7}, {%8,%9}, {%0,%1,%2,%3};"
                    : "+f"(o[dt][0]), "+f"(o[dt][1]), "+f"(o[dt][2]), "+f"(o[dt][3])
                    : "r"(pa0), "r"(pa1), "r"(pa2), "r"(pa3),
                      "r"(b0), "r"(b1));
            }
        }

        // row-sum reduce across quad, normalize, store
        sa += __shfl_xor_sync(0xffffffffu, sa, 1);
        sa += __shfl_xor_sync(0xffffffffu, sa, 2);
        sb += __shfl_xor_sync(0xffffffffu, sb, 1);
        sb += __shfl_xor_sync(0xffffffffu, sb, 2);
        float inva = 1.f / sa, invb = 1.f / sb;

        #pragma unroll
        for (int dt = 0; dt < 4; dt++) {
            int d = dt*8 + 2*tig;
            *(float2*)&ob[(size_t)ra*CH + d] =
                make_float2(o[dt][0]*inva, o[dt][1]*inva);
            if (rb < NTOK)
                *(float2*)&ob[(size_t)rb*CH + d] =
                    make_float2(o[dt][2]*invb, o[dt][3]*invb);
        }
    }
}

// ---------------- launch ----------------
extern "C" void kernel_launch(void* const* d_in, const int* in_sizes, int n_in,
                              void* d_out, int out_size)
{
    const float* x     = (const float*)d_in[0];
    const float* y     = (const float*)d_in[1];
    const float* mask  = (const float*)d_in[2];
    const float* Wqkv  = (const float*)d_in[3];
    const float* bqkv  = (const float*)d_in[4];
    const float* Wproj = (const float*)d_in[5];
    const float* bproj = (const float*)d_in[6];
    const float* ppw   = (const float*)d_in[7];
    const float* ppb   = (const float*)d_in[8];
    const float* g1    = (const float*)d_in[9];
    const float* be1   = (const float*)d_in[10];
    const float* w1    = (const float*)d_in[11];
    const float* b1    = (const float*)d_in[12];
    const float* g2    = (const float*)d_in[13];
    const float* be2   = (const float*)d_in[14];
    const float* w2    = (const float*)d_in[15];
    const float* b2    = (const float*)d_in[16];
    const float* g3    = (const float*)d_in[17];
    const float* be3   = (const float*)d_in[18];
    const float* w3    = (const float*)d_in[19];
    const float* b3    = (const float*)d_in[20];
    float* out = (float*)d_out;

    float *qp, *kvp, *attp;
    cudaGetSymbolAddress((void**)&qp,  g_q);
    cudaGetSymbolAddress((void**)&kvp, g_kv);
    cudaGetSymbolAddress((void**)&attp, g_att);

    pos_mlp_kernel<<<(M_POS+255)/256, 256>>>(ppw, ppb, g1, be1, w1, b1,
                                             g2, be2, w2, b2, g3, be3, w3, b3);
    {
        dim3 grid(CH/64, MROWS/128);
        gemm_tf32_kernel<<<grid, 256>>>(x, Wqkv, bqkv, qp, MROWS, CH, CH);
    }
    {
        dim3 grid((2*CH)/64, MROWS/128);
        gemm_tf32_kernel<<<grid, 256>>>(y, Wqkv + (size_t)CH*CH, bqkv + CH,
                                        kvp, MROWS, 2*CH, CH);
    }
    {
        size_t smem = (size_t)(NTOK*KS_STR + 32*VT_STR + M_POS + NTOK) * 4;
        cudaFuncSetAttribute(attn_tc_kernel, cudaFuncAttributeMaxDynamicSharedMemorySize, (int)smem);
        attn_tc_kernel<<<B_*HEADS, 256, smem>>>(mask);
    }
    {
        dim3 grid(CH/64, MROWS/128);
        gemm_tf32_kernel<<<grid, 256>>>(attp, Wproj, bproj, out, MROWS, CH, CH);
    }
}

// round 9
// speedup vs baseline: 3.9633x; 1.2186x over previous
#include <cuda_runtime.h>
#include <cuda_fp16.h>
#include <math.h>
#include <stdint.h>

#define B_     256
#define NG_    64
#define HEADS  6
#define CH     192
#define NTOK   216
#define HD     32
#define M_POS  1331
#define PDIM   12
#define MROWS  (B_*NTOK)   // 55296

// fp16 attention tiling
#define NKP     224        // keys padded to 14*16
#define KS_STRH 40         // K smem row stride in halves: bank=20*grp+tig, conflict-free
#define VT_STRH 248        // V^T smem row stride in halves: bank=28*grp+tig, conflict-free
#define KT16    14         // 16-key tiles
#define MT      14         // m16 query strips

// ---------------- scratch ----------------
__device__ float g_q  [(size_t)B_*NTOK*CH];
__device__ float g_kv [(size_t)B_*NTOK*2*CH];
__device__ float g_att[(size_t)B_*NTOK*CH];
__device__ float g_pos[HEADS*M_POS];

__device__ __forceinline__ uint32_t f2tf(float f) {
    uint32_t r;
    asm("cvt.rna.tf32.f32 %0, %1;" : "=r"(r) : "f"(f));
    return r;
}
__device__ __forceinline__ uint32_t pack_h2(float a, float b) {
    __half2 h = __floats2half2_rn(a, b);
    return *(uint32_t*)&h;
}

// ---------------- tiny dynamic position-bias MLP ----------------
__device__ __forceinline__ void ln12(float* t, const float* g, const float* b) {
    float mu = 0.f;
    #pragma unroll
    for (int i = 0; i < PDIM; i++) mu += t[i];
    mu *= (1.f/PDIM);
    float v = 0.f;
    #pragma unroll
    for (int i = 0; i < PDIM; i++) { float d = t[i]-mu; v += d*d; }
    v *= (1.f/PDIM);
    float inv = rsqrtf(v + 1e-5f);
    #pragma unroll
    for (int i = 0; i < PDIM; i++) t[i] = (t[i]-mu)*inv*g[i] + b[i];
}

__global__ void pos_mlp_kernel(
    const float* __restrict__ ppw, const float* __restrict__ ppb,
    const float* __restrict__ g1,  const float* __restrict__ be1,
    const float* __restrict__ w1,  const float* __restrict__ b1,
    const float* __restrict__ g2,  const float* __restrict__ be2,
    const float* __restrict__ w2,  const float* __restrict__ b2,
    const float* __restrict__ g3,  const float* __restrict__ be3,
    const float* __restrict__ w3,  const float* __restrict__ b3)
{
    int m = blockIdx.x*blockDim.x + threadIdx.x;
    if (m >= M_POS) return;
    float c0 = (float)(m/121 - 5);
    float c1 = (float)((m/11)%11 - 5);
    float c2 = (float)(m%11 - 5);
    float t[PDIM], u[PDIM];
    #pragma unroll
    for (int i = 0; i < PDIM; i++)
        t[i] = ppw[i*3+0]*c0 + ppw[i*3+1]*c1 + ppw[i*3+2]*c2 + ppb[i];
    ln12(t, g1, be1);
    #pragma unroll
    for (int i = 0; i < PDIM; i++) {
        float acc = b1[i];
        #pragma unroll
        for (int j = 0; j < PDIM; j++) acc += w1[i*PDIM+j]*fmaxf(t[j],0.f);
        u[i] = acc;
    }
    ln12(u, g2, be2);
    #pragma unroll
    for (int i = 0; i < PDIM; i++) {
        float acc = b2[i];
        #pragma unroll
        for (int j = 0; j < PDIM; j++) acc += w2[i*PDIM+j]*fmaxf(u[j],0.f);
        t[i] = acc;
    }
    ln12(t, g3, be3);
    #pragma unroll
    for (int h = 0; h < HEADS; h++) {
        float acc = b3[h];
        #pragma unroll
        for (int j = 0; j < PDIM; j++) acc += w3[h*PDIM+j]*fmaxf(t[j],0.f);
        g_pos[h*M_POS + m] = acc;
    }
}

// ---------------- TF32 tensor-core GEMM (validated R4) ----------------
#define GK 16
#define ASTR 20

__global__ __launch_bounds__(256)
void gemm_tf32_kernel(const float* __restrict__ A, const float* __restrict__ W,
                      const float* __restrict__ bias, float* __restrict__ Cout,
                      int Mdim, int Ndim, int Kdim)
{
    __shared__ uint32_t As[128*ASTR];
    __shared__ uint32_t Ws[64*ASTR];

    int tid  = threadIdx.x;
    int w    = tid >> 5, lane = tid & 31;
    int grp  = lane >> 2, tig = lane & 3;
    int wm   = (w >> 1) * 32;
    int wn   = (w & 1) * 32;
    int m0   = blockIdx.y * 128, n0 = blockIdx.x * 64;

    int arow = tid >> 2;
    int ak   = (tid & 3) * 4;
    const float* Aptr = A + (size_t)(m0 + arow)*Kdim + ak;
    const float* Wptr = W + (size_t)(n0 + arow)*Kdim + ak;

    float4 aR0 = *(const float4*)Aptr;
    float4 aR1 = *(const float4*)(Aptr + (size_t)64*Kdim);
    float4 wR  = *(const float4*)Wptr;

    float acc[2][4][4];
    #pragma unroll
    for (int i = 0; i < 2; i++)
        #pragma unroll
        for (int j = 0; j < 4; j++)
            #pragma unroll
            for (int c = 0; c < 4; c++) acc[i][j][c] = 0.f;

    int nstage = Kdim / GK;

    for (int st = 0;;) {
        {
            uint4 v0 = make_uint4(f2tf(aR0.x), f2tf(aR0.y), f2tf(aR0.z), f2tf(aR0.w));
            uint4 v1 = make_uint4(f2tf(aR1.x), f2tf(aR1.y), f2tf(aR1.z), f2tf(aR1.w));
            uint4 v2 = make_uint4(f2tf(wR.x),  f2tf(wR.y),  f2tf(wR.z),  f2tf(wR.w));
            *(uint4*)&As[(arow     )*ASTR + ak] = v0;
            *(uint4*)&As[(arow + 64)*ASTR + ak] = v1;
            *(uint4*)&Ws[(arow     )*ASTR + ak] = v2;
        }
        __syncthreads();
        st++;
        if (st < nstage) {
            aR0 = *(const float4*)(Aptr + st*GK);
            aR1 = *(const float4*)(Aptr + (size_t)64*Kdim + st*GK);
            wR  = *(const float4*)(Wptr + st*GK);
        }
        #pragma unroll
        for (int ks = 0; ks < 2; ks++) {
            int kb = ks*8;
            uint32_t af[2][4], bf[4][2];
            #pragma unroll
            for (int mf = 0; mf < 2; mf++) {
                int r = wm + mf*16 + grp;
                af[mf][0] = As[(r    )*ASTR + kb + tig];
                af[mf][1] = As[(r + 8)*ASTR + kb + tig];
                af[mf][2] = As[(r    )*ASTR + kb + tig + 4];
                af[mf][3] = As[(r + 8)*ASTR + kb + tig + 4];
            }
            #pragma unroll
            for (int nf = 0; nf < 4; nf++) {
                int n = wn + nf*8 + grp;
                bf[nf][0] = Ws[n*ASTR + kb + tig];
                bf[nf][1] = Ws[n*ASTR + kb + tig + 4];
            }
            #pragma unroll
            for (int mf = 0; mf < 2; mf++)
                #pragma unroll
                for (int nf = 0; nf < 4; nf++) {
                    asm volatile(
                        "mma.sync.aligned.m16n8k8.row.col.f32.tf32.tf32.f32 "
                        "{%0,%1,%2,%3}, {%4,%5,%6,%7}, {%8,%9}, {%0,%1,%2,%3};"
                        : "+f"(acc[mf][nf][0]), "+f"(acc[mf][nf][1]),
                          "+f"(acc[mf][nf][2]), "+f"(acc[mf][nf][3])
                        : "r"(af[mf][0]), "r"(af[mf][1]), "r"(af[mf][2]), "r"(af[mf][3]),
                          "r"(bf[nf][0]), "r"(bf[nf][1]));
                }
        }
        if (st >= nstage) break;
        __syncthreads();
    }

    #pragma unroll
    for (int mf = 0; mf < 2; mf++) {
        #pragma unroll
        for (int nf = 0; nf < 4; nf++) {
            int col = n0 + wn + nf*8 + 2*tig;
            float bx = bias[col], by = bias[col+1];
            int r0 = m0 + wm + mf*16 + grp;
            float2 o0 = make_float2(acc[mf][nf][0] + bx, acc[mf][nf][1] + by);
            float2 o1 = make_float2(acc[mf][nf][2] + bx, acc[mf][nf][3] + by);
            *(float2*)&Cout[(size_t)r0*Ndim + col]       = o0;
            *(float2*)&Cout[(size_t)(r0+8)*Ndim + col]   = o1;
        }
    }
}

// ---------------- fp16 tensor-core fused attention (online, max-free softmax) ----------------
__global__ __launch_bounds__(256)
void attn_tc_kernel(const float* __restrict__ mask)
{
    extern __shared__ __half smh[];
    __half* Ksh = smh;                         // [224][40] half (K, d contiguous)
    __half* Vth = Ksh + NKP*KS_STRH;           // [32][248] half (V^T, keys contiguous)
    float*  posh = (float*)(Vth + 32*VT_STRH); // [1331]
    int*    midv = (int*)(posh + M_POS);       // [216] pid3 LUT

    int bh = blockIdx.x;
    int b  = bh / HEADS, h = bh % HEADS;
    int g  = b & (NG_-1);
    int tid = threadIdx.x;
    int w = tid >> 5, lane = tid & 31;
    int grp = lane >> 2, tig = lane & 3;

    const float* kvb = g_kv + (size_t)b*NTOK*(2*CH);
    for (int e = tid; e < NKP*32; e += 256) {
        int m = e >> 5, d = e & 31;
        float kf = 0.f, vf = 0.f;
        if (m < NTOK) {
            kf = kvb[(size_t)m*(2*CH) + h*32 + d];
            vf = kvb[(size_t)m*(2*CH) + CH + h*32 + d];
        }
        Ksh[m*KS_STRH + d] = __float2half(kf);
        Vth[d*VT_STRH + m] = __float2half(vf);
    }
    for (int e = tid; e < M_POS; e += 256) posh[e] = g_pos[h*M_POS + e];
    for (int e = tid; e < NTOK; e += 256)
        midv[e] = (e/36)*121 + ((e/6)%6)*11 + (e%6);
    __syncthreads();

    const float* maskb = mask + (size_t)g*NTOK*NTOK;
    const float* qb = g_q + (size_t)b*NTOK*CH + h*32;
    float* ob = g_att + (size_t)b*NTOK*CH + h*32;
    const float scale = 0.17677669529663687f;  // 32^-0.5

    for (int strip = w; strip < MT; strip += 8) {
        int n0 = strip*16;
        int ra = n0 + grp, rb = ra + 8;
        int ra_c = min(ra, NTOK-1), rb_c = min(rb, NTOK-1);

        // Q A-frags: 2 d-chunks of k16 (m16n8k16 layout)
        uint32_t aq[2][4];
        const float* qa = qb + (size_t)ra_c*CH;
        const float* qB = qb + (size_t)rb_c*CH;
        #pragma unroll
        for (int c = 0; c < 2; c++) {
            aq[c][0] = pack_h2(qa[c*16 + 2*tig],     qa[c*16 + 2*tig + 1]);
            aq[c][1] = pack_h2(qB[c*16 + 2*tig],     qB[c*16 + 2*tig + 1]);
            aq[c][2] = pack_h2(qa[c*16 + 2*tig + 8], qa[c*16 + 2*tig + 9]);
            aq[c][3] = pack_h2(qB[c*16 + 2*tig + 8], qB[c*16 + 2*tig + 9]);
        }

        int nida = midv[ra_c], nidb = midv[rb_c];
        const float* mra = maskb + (size_t)ra_c*NTOK;
        const float* mrb = maskb + (size_t)rb_c*NTOK;

        float o[4][4];
        #pragma unroll
        for (int dt = 0; dt < 4; dt++)
            #pragma unroll
            for (int c = 0; c < 4; c++) o[dt][c] = 0.f;
        float sa = 0.f, sb = 0.f;

        #pragma unroll 2
        for (int kt = 0; kt < KT16; kt++) {
            // S0 tile: keys kt*16 + 0..7 ; S1 tile: keys kt*16 + 8..15
            float s0c[4] = {0.f,0.f,0.f,0.f};
            float s1c[4] = {0.f,0.f,0.f,0.f};
            int key0 = kt*16 + grp;
            #pragma unroll
            for (int c = 0; c < 2; c++) {
                uint32_t b0 = *(const uint32_t*)&Ksh[(key0    )*KS_STRH + c*16 + 2*tig];
                uint32_t b1 = *(const uint32_t*)&Ksh[(key0    )*KS_STRH + c*16 + 2*tig + 8];
                uint32_t d0 = *(const uint32_t*)&Ksh[(key0 + 8)*KS_STRH + c*16 + 2*tig];
                uint32_t d1 = *(const uint32_t*)&Ksh[(key0 + 8)*KS_STRH + c*16 + 2*tig + 8];
                asm volatile(
                    "mma.sync.aligned.m16n8k16.row.col.f32.f16.f16.f32 "
                    "{%0,%1,%2,%3}, {%4,%5,%6,%7}, {%8,%9}, {%0,%1,%2,%3};"
                    : "+f"(s0c[0]), "+f"(s0c[1]), "+f"(s0c[2]), "+f"(s0c[3])
                    : "r"(aq[c][0]), "r"(aq[c][1]), "r"(aq[c][2]), "r"(aq[c][3]),
                      "r"(b0), "r"(b1));
                asm volatile(
                    "mma.sync.aligned.m16n8k16.row.col.f32.f16.f16.f32 "
                    "{%0,%1,%2,%3}, {%4,%5,%6,%7}, {%8,%9}, {%0,%1,%2,%3};"
                    : "+f"(s1c[0]), "+f"(s1c[1]), "+f"(s1c[2]), "+f"(s1c[3])
                    : "r"(aq[c][0]), "r"(aq[c][1]), "r"(aq[c][2]), "r"(aq[c][3]),
                      "r"(d0), "r"(d1));
            }

            // bias + mask + exp (fp32), accumulate row sums, pack P A-frags directly
            uint32_t pa0, pa1, pa2, pa3;
            {
                int m0 = kt*16 + 2*tig;
                int mid0 = midv[m0], mid1 = midv[m0+1];
                float2 ma = *(const float2*)(mra + m0);
                float2 mb = *(const float2*)(mrb + m0);
                float p00 = __expf(s0c[0]*scale + posh[nida - mid0 + 665] + ma.x);
                float p01 = __expf(s0c[1]*scale + posh[nida - mid1 + 665] + ma.y);
                float p02 = __expf(s0c[2]*scale + posh[nidb - mid0 + 665] + mb.x);
                float p03 = __expf(s0c[3]*scale + posh[nidb - mid1 + 665] + mb.y);
                sa += p00 + p01;
                sb += p02 + p03;
                pa0 = pack_h2(p00, p01);
                pa1 = pack_h2(p02, p03);
            }
            if (kt < KT16-1) {     // uniform branch; last tile's upper n8 is padding
                int m1 = kt*16 + 8 + 2*tig;
                int mid0 = midv[m1], mid1 = midv[m1+1];
                float2 ma = *(const float2*)(mra + m1);
                float2 mb = *(const float2*)(mrb + m1);
                float p10 = __expf(s1c[0]*scale + posh[nida - mid0 + 665] + ma.x);
                float p11 = __expf(s1c[1]*scale + posh[nida - mid1 + 665] + ma.y);
                float p12 = __expf(s1c[2]*scale + posh[nidb - mid0 + 665] + mb.x);
                float p13 = __expf(s1c[3]*scale + posh[nidb - mid1 + 665] + mb.y);
                sa += p10 + p11;
                sb += p12 + p13;
                pa2 = pack_h2(p10, p11);
                pa3 = pack_h2(p12, p13);
            } else {
                pa2 = 0u; pa3 = 0u;
            }

            // O += P V   (P A-frag built in-place, V^T B-frags from SMEM)
            #pragma unroll
            for (int dt = 0; dt < 4; dt++) {
                uint32_t b0 = *(const uint32_t*)&Vth[(dt*8 + grp)*VT_STRH + kt*16 + 2*tig];
                uint32_t b1 = *(const uint32_t*)&Vth[(dt*8 + grp)*VT_STRH + kt*16 + 2*tig + 8];
                asm volatile(
                    "mma.sync.aligned.m16n8k16.row.col.f32.f16.f16.f32 "
                    "{%0,%1,%2,%3}, {%4,%5,%6,%7}, {%8,%9}, {%0,%1,%2,%3};"
                    : "+f"(o[dt][0]), "+f"(o[dt][1]), "+f"(o[dt][2]), "+f"(o[dt][3])
                    : "r"(pa0), "r"(pa1), "r"(pa2), "r"(pa3),
                      "r"(b0), "r"(b1));
            }
        }

        // row-sum reduce across quad, normalize, store
        sa += __shfl_xor_sync(0xffffffffu, sa, 1);
        sa += __shfl_xor_sync(0xffffffffu, sa, 2);
        sb += __shfl_xor_sync(0xffffffffu, sb, 1);
        sb += __shfl_xor_sync(0xffffffffu, sb, 2);
        float inva = 1.f / sa, invb = 1.f / sb;

        #pragma unroll
        for (int dt = 0; dt < 4; dt++) {
            int d = dt*8 + 2*tig;
            *(float2*)&ob[(size_t)ra*CH + d] =
                make_float2(o[dt][0]*inva, o[dt][1]*inva);
            if (rb < NTOK)
                *(float2*)&ob[(size_t)rb*CH + d] =
                    make_float2(o[dt][2]*invb, o[dt][3]*invb);
        }
    }
}

// ---------------- launch ----------------
extern "C" void kernel_launch(void* const* d_in, const int* in_sizes, int n_in,
                              void* d_out, int out_size)
{
    const float* x     = (const float*)d_in[0];
    const float* y     = (const float*)d_in[1];
    const float* mask  = (const float*)d_in[2];
    const float* Wqkv  = (const float*)d_in[3];
    const float* bqkv  = (const float*)d_in[4];
    const float* Wproj = (const float*)d_in[5];
    const float* bproj = (const float*)d_in[6];
    const float* ppw   = (const float*)d_in[7];
    const float* ppb   = (const float*)d_in[8];
    const float* g1    = (const float*)d_in[9];
    const float* be1   = (const float*)d_in[10];
    const float* w1    = (const float*)d_in[11];
    const float* b1    = (const float*)d_in[12];
    const float* g2    = (const float*)d_in[13];
    const float* be2   = (const float*)d_in[14];
    const float* w2    = (const float*)d_in[15];
    const float* b2    = (const float*)d_in[16];
    const float* g3    = (const float*)d_in[17];
    const float* be3   = (const float*)d_in[18];
    const float* w3    = (const float*)d_in[19];
    const float* b3    = (const float*)d_in[20];
    float* out = (float*)d_out;

    float *qp, *kvp, *attp;
    cudaGetSymbolAddress((void**)&qp,  g_q);
    cudaGetSymbolAddress((void**)&kvp, g_kv);
    cudaGetSymbolAddress((void**)&attp, g_att);

    pos_mlp_kernel<<<(M_POS+255)/256, 256>>>(ppw, ppb, g1, be1, w1, b1,
                                             g2, be2, w2, b2, g3, be3, w3, b3);
    {
        dim3 grid(CH/64, MROWS/128);
        gemm_tf32_kernel<<<grid, 256>>>(x, Wqkv, bqkv, qp, MROWS, CH, CH);
    }
    {
        dim3 grid((2*CH)/64, MROWS/128);
        gemm_tf32_kernel<<<grid, 256>>>(y, Wqkv + (size_t)CH*CH, bqkv + CH,
                                        kvp, MROWS, 2*CH, CH);
    }
    {
        size_t smem = (size_t)(NKP*KS_STRH + 32*VT_STRH)*2 + (size_t)(M_POS + NTOK)*4;
        cudaFuncSetAttribute(attn_tc_kernel, cudaFuncAttributeMaxDynamicSharedMemorySize, (int)smem);
        attn_tc_kernel<<<B_*HEADS, 256, smem>>>(mask);
    }
    {
        dim3 grid(CH/64, MROWS/128);
        gemm_tf32_kernel<<<grid, 256>>>(attp, Wproj, bproj, out, MROWS, CH, CH);
    }
}

// round 10
// speedup vs baseline: 4.7345x; 1.1946x over previous
#include <cuda_runtime.h>
#include <cuda_fp16.h>
#include <math.h>
#include <stdint.h>

#define B_     256
#define NG_    64
#define HEADS  6
#define CH     192
#define NTOK   216
#define HD     32
#define M_POS  1331
#define PDIM   12
#define MROWS  (B_*NTOK)   // 55296

// fp16 attention tiling
#define NKP     224        // keys padded to 14*16
#define KS_STRH 40         // K smem row stride in halves: conflict-free frag loads
#define VT_STRH 248        // V^T smem row stride in halves: conflict-free frag loads
#define KT16    14         // 16-key tiles
#define MT      14         // m16 query strips

// fp16 GEMM tiling
#define HSTR    24         // SMEM row stride in halves (bank = 12r + tig, conflict-free loads)

// ---------------- scratch ----------------
__device__ float g_q  [(size_t)B_*NTOK*CH];
__device__ float g_kv [(size_t)B_*NTOK*2*CH];
__device__ float g_att[(size_t)B_*NTOK*CH];
__device__ float g_pos[HEADS*M_POS];

__device__ __forceinline__ uint32_t pack_h2(float a, float b) {
    __half2 h = __floats2half2_rn(a, b);
    return *(uint32_t*)&h;
}

// ---------------- tiny dynamic position-bias MLP ----------------
__device__ __forceinline__ void ln12(float* t, const float* g, const float* b) {
    float mu = 0.f;
    #pragma unroll
    for (int i = 0; i < PDIM; i++) mu += t[i];
    mu *= (1.f/PDIM);
    float v = 0.f;
    #pragma unroll
    for (int i = 0; i < PDIM; i++) { float d = t[i]-mu; v += d*d; }
    v *= (1.f/PDIM);
    float inv = rsqrtf(v + 1e-5f);
    #pragma unroll
    for (int i = 0; i < PDIM; i++) t[i] = (t[i]-mu)*inv*g[i] + b[i];
}

__global__ void pos_mlp_kernel(
    const float* __restrict__ ppw, const float* __restrict__ ppb,
    const float* __restrict__ g1,  const float* __restrict__ be1,
    const float* __restrict__ w1,  const float* __restrict__ b1,
    const float* __restrict__ g2,  const float* __restrict__ be2,
    const float* __restrict__ w2,  const float* __restrict__ b2,
    const float* __restrict__ g3,  const float* __restrict__ be3,
    const float* __restrict__ w3,  const float* __restrict__ b3)
{
    int m = blockIdx.x*blockDim.x + threadIdx.x;
    if (m >= M_POS) return;
    float c0 = (float)(m/121 - 5);
    float c1 = (float)((m/11)%11 - 5);
    float c2 = (float)(m%11 - 5);
    float t[PDIM], u[PDIM];
    #pragma unroll
    for (int i = 0; i < PDIM; i++)
        t[i] = ppw[i*3+0]*c0 + ppw[i*3+1]*c1 + ppw[i*3+2]*c2 + ppb[i];
    ln12(t, g1, be1);
    #pragma unroll
    for (int i = 0; i < PDIM; i++) {
        float acc = b1[i];
        #pragma unroll
        for (int j = 0; j < PDIM; j++) acc += w1[i*PDIM+j]*fmaxf(t[j],0.f);
        u[i] = acc;
    }
    ln12(u, g2, be2);
    #pragma unroll
    for (int i = 0; i < PDIM; i++) {
        float acc = b2[i];
        #pragma unroll
        for (int j = 0; j < PDIM; j++) acc += w2[i*PDIM+j]*fmaxf(u[j],0.f);
        t[i] = acc;
    }
    ln12(t, g3, be3);
    #pragma unroll
    for (int h = 0; h < HEADS; h++) {
        float acc = b3[h];
        #pragma unroll
        for (int j = 0; j < PDIM; j++) acc += w3[h*PDIM+j]*fmaxf(t[j],0.f);
        g_pos[h*M_POS + m] = acc;
    }
}

// ---------------- FP16 tensor-core GEMM ----------------
// C[m][n] = sum_k A[m][k]*W[n][k] + bias[n]
// 128x64 CTA tile, 256 threads (8 warps 4x2), warp tile 32x32, mma.m16n8k16.f16, fp32 accum.
__global__ __launch_bounds__(256)
void gemm_f16_kernel(const float* __restrict__ A, const float* __restrict__ W,
                     const float* __restrict__ bias, float* __restrict__ Cout,
                     int Mdim, int Ndim, int Kdim)
{
    __shared__ uint32_t As[128*HSTR/2];   // [128][24] halves
    __shared__ uint32_t Ws[64*HSTR/2];    // [64][24] halves

    int tid  = threadIdx.x;
    int w    = tid >> 5, lane = tid & 31;
    int grp  = lane >> 2, tig = lane & 3;
    int wm   = (w >> 1) * 32;
    int wn   = (w & 1) * 32;
    int m0   = blockIdx.y * 128, n0 = blockIdx.x * 64;

    int arow = tid >> 2;                 // 0..63
    int ak   = (tid & 3) * 4;            // 0,4,8,12
    const float* Aptr = A + (size_t)(m0 + arow)*Kdim + ak;
    const float* Wptr = W + (size_t)(n0 + arow)*Kdim + ak;

    float4 aR0 = *(const float4*)Aptr;
    float4 aR1 = *(const float4*)(Aptr + (size_t)64*Kdim);
    float4 wR  = *(const float4*)Wptr;

    float acc[2][4][4];
    #pragma unroll
    for (int i = 0; i < 2; i++)
        #pragma unroll
        for (int j = 0; j < 4; j++)
            #pragma unroll
            for (int c = 0; c < 4; c++) acc[i][j][c] = 0.f;

    int nstage = Kdim >> 4;   // 12 stages of k16

    for (int st = 0;;) {
        {
            uint2 v0 = make_uint2(pack_h2(aR0.x, aR0.y), pack_h2(aR0.z, aR0.w));
            uint2 v1 = make_uint2(pack_h2(aR1.x, aR1.y), pack_h2(aR1.z, aR1.w));
            uint2 v2 = make_uint2(pack_h2(wR.x,  wR.y),  pack_h2(wR.z,  wR.w));
            *(uint2*)&As[(arow     )*(HSTR/2) + ak/2] = v0;
            *(uint2*)&As[(arow + 64)*(HSTR/2) + ak/2] = v1;
            *(uint2*)&Ws[(arow     )*(HSTR/2) + ak/2] = v2;
        }
        __syncthreads();
        st++;
        if (st < nstage) {
            aR0 = *(const float4*)(Aptr + st*16);
            aR1 = *(const float4*)(Aptr + (size_t)64*Kdim + st*16);
            wR  = *(const float4*)(Wptr + st*16);
        }
        // one k16 step: 2 m-tiles x 4 n-tiles
        {
            uint32_t af[2][4], bf[4][2];
            #pragma unroll
            for (int mf = 0; mf < 2; mf++) {
                int r = wm + mf*16 + grp;
                af[mf][0] = As[(r    )*(HSTR/2) + tig];
                af[mf][1] = As[(r + 8)*(HSTR/2) + tig];
                af[mf][2] = As[(r    )*(HSTR/2) + tig + 4];
                af[mf][3] = As[(r + 8)*(HSTR/2) + tig + 4];
            }
            #pragma unroll
            for (int nf = 0; nf < 4; nf++) {
                int n = wn + nf*8 + grp;
                bf[nf][0] = Ws[n*(HSTR/2) + tig];
                bf[nf][1] = Ws[n*(HSTR/2) + tig + 4];
            }
            #pragma unroll
            for (int mf = 0; mf < 2; mf++)
                #pragma unroll
                for (int nf = 0; nf < 4; nf++) {
                    asm volatile(
                        "mma.sync.aligned.m16n8k16.row.col.f32.f16.f16.f32 "
                        "{%0,%1,%2,%3}, {%4,%5,%6,%7}, {%8,%9}, {%0,%1,%2,%3};"
                        : "+f"(acc[mf][nf][0]), "+f"(acc[mf][nf][1]),
                          "+f"(acc[mf][nf][2]), "+f"(acc[mf][nf][3])
                        : "r"(af[mf][0]), "r"(af[mf][1]), "r"(af[mf][2]), "r"(af[mf][3]),
                          "r"(bf[nf][0]), "r"(bf[nf][1]));
                }
        }
        if (st >= nstage) break;
        __syncthreads();
    }

    #pragma unroll
    for (int mf = 0; mf < 2; mf++) {
        #pragma unroll
        for (int nf = 0; nf < 4; nf++) {
            int col = n0 + wn + nf*8 + 2*tig;
            float bx = bias[col], by = bias[col+1];
            int r0 = m0 + wm + mf*16 + grp;
            float2 o0 = make_float2(acc[mf][nf][0] + bx, acc[mf][nf][1] + by);
            float2 o1 = make_float2(acc[mf][nf][2] + bx, acc[mf][nf][3] + by);
            *(float2*)&Cout[(size_t)r0*Ndim + col]       = o0;
            *(float2*)&Cout[(size_t)(r0+8)*Ndim + col]   = o1;
        }
    }
}

// ---------------- fp16 tensor-core fused attention (online, max-free softmax) ----------------
__global__ __launch_bounds__(256)
void attn_tc_kernel(const float* __restrict__ mask)
{
    extern __shared__ __half smh[];
    __half* Ksh = smh;                         // [224][40] half (K, d contiguous)
    __half* Vth = Ksh + NKP*KS_STRH;           // [32][248] half (V^T, keys contiguous)
    float*  posh = (float*)(Vth + 32*VT_STRH); // [1331]
    int*    midv = (int*)(posh + M_POS);       // [216] pid3 LUT

    int bh = blockIdx.x;
    int b  = bh / HEADS, h = bh % HEADS;
    int g  = b & (NG_-1);
    int tid = threadIdx.x;
    int w = tid >> 5, lane = tid & 31;
    int grp = lane >> 2, tig = lane & 3;

    const float* kvb = g_kv + (size_t)b*NTOK*(2*CH);
    for (int e = tid; e < NKP*32; e += 256) {
        int m = e >> 5, d = e & 31;
        float kf = 0.f, vf = 0.f;
        if (m < NTOK) {
            kf = kvb[(size_t)m*(2*CH) + h*32 + d];
            vf = kvb[(size_t)m*(2*CH) + CH + h*32 + d];
        }
        Ksh[m*KS_STRH + d] = __float2half(kf);
        Vth[d*VT_STRH + m] = __float2half(vf);
    }
    for (int e = tid; e < M_POS; e += 256) posh[e] = g_pos[h*M_POS + e];
    for (int e = tid; e < NTOK; e += 256)
        midv[e] = (e/36)*121 + ((e/6)%6)*11 + (e%6);
    __syncthreads();

    const float* maskb = mask + (size_t)g*NTOK*NTOK;
    const float* qb = g_q + (size_t)b*NTOK*CH + h*32;
    float* ob = g_att + (size_t)b*NTOK*CH + h*32;
    const float scale = 0.17677669529663687f;  // 32^-0.5

    for (int strip = w; strip < MT; strip += 8) {
        int n0 = strip*16;
        int ra = n0 + grp, rb = ra + 8;
        int ra_c = min(ra, NTOK-1), rb_c = min(rb, NTOK-1);

        // Q A-frags: 2 d-chunks of k16
        uint32_t aq[2][4];
        const float* qa = qb + (size_t)ra_c*CH;
        const float* qB = qb + (size_t)rb_c*CH;
        #pragma unroll
        for (int c = 0; c < 2; c++) {
            aq[c][0] = pack_h2(qa[c*16 + 2*tig],     qa[c*16 + 2*tig + 1]);
            aq[c][1] = pack_h2(qB[c*16 + 2*tig],     qB[c*16 + 2*tig + 1]);
            aq[c][2] = pack_h2(qa[c*16 + 2*tig + 8], qa[c*16 + 2*tig + 9]);
            aq[c][3] = pack_h2(qB[c*16 + 2*tig + 8], qB[c*16 + 2*tig + 9]);
        }

        int nida = midv[ra_c], nidb = midv[rb_c];
        const float* mra = maskb + (size_t)ra_c*NTOK;
        const float* mrb = maskb + (size_t)rb_c*NTOK;

        float o[4][4];
        #pragma unroll
        for (int dt = 0; dt < 4; dt++)
            #pragma unroll
            for (int c = 0; c < 4; c++) o[dt][c] = 0.f;
        float sa = 0.f, sb = 0.f;

        #pragma unroll 2
        for (int kt = 0; kt < KT16; kt++) {
            float s0c[4] = {0.f,0.f,0.f,0.f};
            float s1c[4] = {0.f,0.f,0.f,0.f};
            int key0 = kt*16 + grp;
            #pragma unroll
            for (int c = 0; c < 2; c++) {
                uint32_t b0 = *(const uint32_t*)&Ksh[(key0    )*KS_STRH + c*16 + 2*tig];
                uint32_t b1 = *(const uint32_t*)&Ksh[(key0    )*KS_STRH + c*16 + 2*tig + 8];
                uint32_t d0 = *(const uint32_t*)&Ksh[(key0 + 8)*KS_STRH + c*16 + 2*tig];
                uint32_t d1 = *(const uint32_t*)&Ksh[(key0 + 8)*KS_STRH + c*16 + 2*tig + 8];
                asm volatile(
                    "mma.sync.aligned.m16n8k16.row.col.f32.f16.f16.f32 "
                    "{%0,%1,%2,%3}, {%4,%5,%6,%7}, {%8,%9}, {%0,%1,%2,%3};"
                    : "+f"(s0c[0]), "+f"(s0c[1]), "+f"(s0c[2]), "+f"(s0c[3])
                    : "r"(aq[c][0]), "r"(aq[c][1]), "r"(aq[c][2]), "r"(aq[c][3]),
                      "r"(b0), "r"(b1));
                asm volatile(
                    "mma.sync.aligned.m16n8k16.row.col.f32.f16.f16.f32 "
                    "{%0,%1,%2,%3}, {%4,%5,%6,%7}, {%8,%9}, {%0,%1,%2,%3};"
                    : "+f"(s1c[0]), "+f"(s1c[1]), "+f"(s1c[2]), "+f"(s1c[3])
                    : "r"(aq[c][0]), "r"(aq[c][1]), "r"(aq[c][2]), "r"(aq[c][3]),
                      "r"(d0), "r"(d1));
            }

            uint32_t pa0, pa1, pa2, pa3;
            {
                int m0 = kt*16 + 2*tig;
                int mid0 = midv[m0], mid1 = midv[m0+1];
                float2 ma = *(const float2*)(mra + m0);
                float2 mb = *(const float2*)(mrb + m0);
                float p00 = __expf(s0c[0]*scale + posh[nida - mid0 + 665] + ma.x);
                float p01 = __expf(s0c[1]*scale + posh[nida - mid1 + 665] + ma.y);
                float p02 = __expf(s0c[2]*scale + posh[nidb - mid0 + 665] + mb.x);
                float p03 = __expf(s0c[3]*scale + posh[nidb - mid1 + 665] + mb.y);
                sa += p00 + p01;
                sb += p02 + p03;
                pa0 = pack_h2(p00, p01);
                pa1 = pack_h2(p02, p03);
            }
            if (kt < KT16-1) {
                int m1 = kt*16 + 8 + 2*tig;
                int mid0 = midv[m1], mid1 = midv[m1+1];
                float2 ma = *(const float2*)(mra + m1);
                float2 mb = *(const float2*)(mrb + m1);
                float p10 = __expf(s1c[0]*scale + posh[nida - mid0 + 665] + ma.x);
                float p11 = __expf(s1c[1]*scale + posh[nida - mid1 + 665] + ma.y);
                float p12 = __expf(s1c[2]*scale + posh[nidb - mid0 + 665] + mb.x);
                float p13 = __expf(s1c[3]*scale + posh[nidb - mid1 + 665] + mb.y);
                sa += p10 + p11;
                sb += p12 + p13;
                pa2 = pack_h2(p10, p11);
                pa3 = pack_h2(p12, p13);
            } else {
                pa2 = 0u; pa3 = 0u;
            }

            #pragma unroll
            for (int dt = 0; dt < 4; dt++) {
                uint32_t b0 = *(const uint32_t*)&Vth[(dt*8 + grp)*VT_STRH + kt*16 + 2*tig];
                uint32_t b1 = *(const uint32_t*)&Vth[(dt*8 + grp)*VT_STRH + kt*16 + 2*tig + 8];
                asm volatile(
                    "mma.sync.aligned.m16n8k16.row.col.f32.f16.f16.f32 "
                    "{%0,%1,%2,%3}, {%4,%5,%6,%7}, {%8,%9}, {%0,%1,%2,%3};"
                    : "+f"(o[dt][0]), "+f"(o[dt][1]), "+f"(o[dt][2]), "+f"(o[dt][3])
                    : "r"(pa0), "r"(pa1), "r"(pa2), "r"(pa3),
                      "r"(b0), "r"(b1));
            }
        }

        sa += __shfl_xor_sync(0xffffffffu, sa, 1);
        sa += __shfl_xor_sync(0xffffffffu, sa, 2);
        sb += __shfl_xor_sync(0xffffffffu, sb, 1);
        sb += __shfl_xor_sync(0xffffffffu, sb, 2);
        float inva = 1.f / sa, invb = 1.f / sb;

        #pragma unroll
        for (int dt = 0; dt < 4; dt++) {
            int d = dt*8 + 2*tig;
            *(float2*)&ob[(size_t)ra*CH + d] =
                make_float2(o[dt][0]*inva, o[dt][1]*inva);
            if (rb < NTOK)
                *(float2*)&ob[(size_t)rb*CH + d] =
                    make_float2(o[dt][2]*invb, o[dt][3]*invb);
        }
    }
}

// ---------------- launch ----------------
extern "C" void kernel_launch(void* const* d_in, const int* in_sizes, int n_in,
                              void* d_out, int out_size)
{
    const float* x     = (const float*)d_in[0];
    const float* y     = (const float*)d_in[1];
    const float* mask  = (const float*)d_in[2];
    const float* Wqkv  = (const float*)d_in[3];
    const float* bqkv  = (const float*)d_in[4];
    const float* Wproj = (const float*)d_in[5];
    const float* bproj = (const float*)d_in[6];
    const float* ppw   = (const float*)d_in[7];
    const float* ppb   = (const float*)d_in[8];
    const float* g1    = (const float*)d_in[9];
    const float* be1   = (const float*)d_in[10];
    const float* w1    = (const float*)d_in[11];
    const float* b1    = (const float*)d_in[12];
    const float* g2    = (const float*)d_in[13];
    const float* be2   = (const float*)d_in[14];
    const float* w2    = (const float*)d_in[15];
    const float* b2    = (const float*)d_in[16];
    const float* g3    = (const float*)d_in[17];
    const float* be3   = (const float*)d_in[18];
    const float* w3    = (const float*)d_in[19];
    const float* b3    = (const float*)d_in[20];
    float* out = (float*)d_out;

    float *qp, *kvp, *attp;
    cudaGetSymbolAddress((void**)&qp,  g_q);
    cudaGetSymbolAddress((void**)&kvp, g_kv);
    cudaGetSymbolAddress((void**)&attp, g_att);

    pos_mlp_kernel<<<(M_POS+255)/256, 256>>>(ppw, ppb, g1, be1, w1, b1,
                                             g2, be2, w2, b2, g3, be3, w3, b3);
    {
        dim3 grid(CH/64, MROWS/128);
        gemm_f16_kernel<<<grid, 256>>>(x, Wqkv, bqkv, qp, MROWS, CH, CH);
    }
    {
        dim3 grid((2*CH)/64, MROWS/128);
        gemm_f16_kernel<<<grid, 256>>>(y, Wqkv + (size_t)CH*CH, bqkv + CH,
                                       kvp, MROWS, 2*CH, CH);
    }
    {
        size_t smem = (size_t)(NKP*KS_STRH + 32*VT_STRH)*2 + (size_t)(M_POS + NTOK)*4;
        cudaFuncSetAttribute(attn_tc_kernel, cudaFuncAttributeMaxDynamicSharedMemorySize, (int)smem);
        attn_tc_kernel<<<B_*HEADS, 256, smem>>>(mask);
    }
    {
        dim3 grid(CH/64, MROWS/128);
        gemm_f16_kernel<<<grid, 256>>>(attp, Wproj, bproj, out, MROWS, CH, CH);
    }
}

// round 11
// speedup vs baseline: 5.7887x; 1.2226x over previous
#include <cuda_runtime.h>
#include <cuda_fp16.h>
#include <math.h>
#include <stdint.h>

#define B_     256
#define NG_    64
#define HEADS  6
#define CH     192
#define NTOK   216
#define HD     32
#define M_POS  1331
#define PDIM   12
#define MROWS  (B_*NTOK)   // 55296

// fp16 attention tiling
#define NKP     224        // keys padded to 14*16
#define KS_STRH 40         // K smem row stride in halves: conflict-free frag loads
#define VT_STRH 248        // V^T smem row stride in halves: conflict-free frag loads
#define KT16    14         // 16-key tiles
#define MT      14         // m16 query strips

// fp16 GEMM (A-resident) tiling
#define AHS     200        // A smem row stride in halves (bank 4*grp+tig, conflict-free)
#define WSTH    24         // W stage row stride in halves
#define GSMEM   ((128*AHS + 2*64*WSTH)*2)   // 57344 B

// ---------------- scratch (all intermediates fp16) ----------------
__device__ __half g_qh  [(size_t)MROWS*CH];
__device__ __half g_kvh [(size_t)MROWS*2*CH];
__device__ __half g_atth[(size_t)MROWS*CH];
__device__ float  g_pos [HEADS*M_POS];

__device__ __forceinline__ uint32_t pack_h2(float a, float b) {
    __half2 h = __floats2half2_rn(a, b);
    return *(uint32_t*)&h;
}

// ---------------- tiny dynamic position-bias MLP ----------------
__device__ __forceinline__ void ln12(float* t, const float* g, const float* b) {
    float mu = 0.f;
    #pragma unroll
    for (int i = 0; i < PDIM; i++) mu += t[i];
    mu *= (1.f/PDIM);
    float v = 0.f;
    #pragma unroll
    for (int i = 0; i < PDIM; i++) { float d = t[i]-mu; v += d*d; }
    v *= (1.f/PDIM);
    float inv = rsqrtf(v + 1e-5f);
    #pragma unroll
    for (int i = 0; i < PDIM; i++) t[i] = (t[i]-mu)*inv*g[i] + b[i];
}

__global__ void pos_mlp_kernel(
    const float* __restrict__ ppw, const float* __restrict__ ppb,
    const float* __restrict__ g1,  const float* __restrict__ be1,
    const float* __restrict__ w1,  const float* __restrict__ b1,
    const float* __restrict__ g2,  const float* __restrict__ be2,
    const float* __restrict__ w2,  const float* __restrict__ b2,
    const float* __restrict__ g3,  const float* __restrict__ be3,
    const float* __restrict__ w3,  const float* __restrict__ b3)
{
    int m = blockIdx.x*blockDim.x + threadIdx.x;
    if (m >= M_POS) return;
    float c0 = (float)(m/121 - 5);
    float c1 = (float)((m/11)%11 - 5);
    float c2 = (float)(m%11 - 5);
    float t[PDIM], u[PDIM];
    #pragma unroll
    for (int i = 0; i < PDIM; i++)
        t[i] = ppw[i*3+0]*c0 + ppw[i*3+1]*c1 + ppw[i*3+2]*c2 + ppb[i];
    ln12(t, g1, be1);
    #pragma unroll
    for (int i = 0; i < PDIM; i++) {
        float acc = b1[i];
        #pragma unroll
        for (int j = 0; j < PDIM; j++) acc += w1[i*PDIM+j]*fmaxf(t[j],0.f);
        u[i] = acc;
    }
    ln12(u, g2, be2);
    #pragma unroll
    for (int i = 0; i < PDIM; i++) {
        float acc = b2[i];
        #pragma unroll
        for (int j = 0; j < PDIM; j++) acc += w2[i*PDIM+j]*fmaxf(u[j],0.f);
        t[i] = acc;
    }
    ln12(t, g3, be3);
    #pragma unroll
    for (int h = 0; h < HEADS; h++) {
        float acc = b3[h];
        #pragma unroll
        for (int j = 0; j < PDIM; j++) acc += w3[h*PDIM+j]*fmaxf(t[j],0.f);
        g_pos[h*M_POS + m] = acc;
    }
}

// ---------------- FP16 tensor-core GEMM, A-resident over full K=192 ----------------
// C[m][n] = sum_k A[m][k]*W[n][k] + bias[n].  One CTA owns 128 rows, loops all N/64 blocks.
template<bool A_HALF, bool OUT_HALF>
__global__ __launch_bounds__(256)
void gemm_f16_big(const void* __restrict__ Ain, const float* __restrict__ W,
                  const float* __restrict__ bias, void* __restrict__ Cout, int Ndim)
{
    extern __shared__ __half sg[];
    __half* Ah  = sg;                 // [128][AHS]
    __half* Wst = Ah + 128*AHS;       // [2][64][WSTH]

    int tid  = threadIdx.x;
    int w    = tid >> 5, lane = tid & 31;
    int grp  = lane >> 2, tig = lane & 3;
    int wm   = (w >> 1) * 32;
    int wn   = (w & 1) * 32;
    int m0   = blockIdx.x * 128;

    // load entire A stripe (128 x 192) into SMEM as half
    if (A_HALF) {
        const __half* Af = (const __half*)Ain + (size_t)m0*CH;
        #pragma unroll
        for (int i = 0; i < 24; i++) {
            int idx = i*256 + tid;
            int row = idx/48, c4 = idx%48;
            uint2 v = *(const uint2*)(Af + (size_t)row*CH + c4*4);
            *(uint2*)&Ah[row*AHS + c4*4] = v;
        }
    } else {
        const float* Af = (const float*)Ain + (size_t)m0*CH;
        #pragma unroll
        for (int i = 0; i < 24; i++) {
            int idx = i*256 + tid;
            int row = idx/48, c4 = idx%48;
            float4 v = *(const float4*)(Af + (size_t)row*CH + c4*4);
            uint2 p = make_uint2(pack_h2(v.x, v.y), pack_h2(v.z, v.w));
            *(uint2*)&Ah[row*AHS + c4*4] = p;
        }
    }
    __syncthreads();

    int wrow = tid >> 2;            // 0..63
    int wk   = (tid & 3) * 4;       // 0,4,8,12
    const uint32_t* Ahw = (const uint32_t*)Ah;
    int nbc = Ndim >> 6;

    for (int nb = 0; nb < nbc; nb++) {
        int n0 = nb*64;
        const float* Wb = W + (size_t)(n0 + wrow)*CH + wk;
        float4 wR = *(const float4*)Wb;

        float acc[2][4][4];
        #pragma unroll
        for (int i = 0; i < 2; i++)
            #pragma unroll
            for (int j = 0; j < 4; j++)
                #pragma unroll
                for (int c = 0; c < 4; c++) acc[i][j][c] = 0.f;

        #pragma unroll
        for (int st = 0; st < 12; st++) {
            __half* Wsb = Wst + (st & 1)*64*WSTH;
            uint2 p = make_uint2(pack_h2(wR.x, wR.y), pack_h2(wR.z, wR.w));
            *(uint2*)&Wsb[wrow*WSTH + wk] = p;
            __syncthreads();
            if (st < 11) wR = *(const float4*)(Wb + (st+1)*16);

            const uint32_t* Wsw = (const uint32_t*)Wsb;
            uint32_t af[2][4], bf[4][2];
            #pragma unroll
            for (int mf = 0; mf < 2; mf++) {
                int r = wm + mf*16 + grp;
                af[mf][0] = Ahw[(r    )*(AHS/2) + st*8 + tig];
                af[mf][1] = Ahw[(r + 8)*(AHS/2) + st*8 + tig];
                af[mf][2] = Ahw[(r    )*(AHS/2) + st*8 + tig + 4];
                af[mf][3] = Ahw[(r + 8)*(AHS/2) + st*8 + tig + 4];
            }
            #pragma unroll
            for (int nf = 0; nf < 4; nf++) {
                int n = wn + nf*8 + grp;
                bf[nf][0] = Wsw[n*(WSTH/2) + tig];
                bf[nf][1] = Wsw[n*(WSTH/2) + tig + 4];
            }
            #pragma unroll
            for (int mf = 0; mf < 2; mf++)
                #pragma unroll
                for (int nf = 0; nf < 4; nf++) {
                    asm volatile(
                        "mma.sync.aligned.m16n8k16.row.col.f32.f16.f16.f32 "
                        "{%0,%1,%2,%3}, {%4,%5,%6,%7}, {%8,%9}, {%0,%1,%2,%3};"
                        : "+f"(acc[mf][nf][0]), "+f"(acc[mf][nf][1]),
                          "+f"(acc[mf][nf][2]), "+f"(acc[mf][nf][3])
                        : "r"(af[mf][0]), "r"(af[mf][1]), "r"(af[mf][2]), "r"(af[mf][3]),
                          "r"(bf[nf][0]), "r"(bf[nf][1]));
                }
        }

        // epilogue for this n-block
        #pragma unroll
        for (int mf = 0; mf < 2; mf++) {
            #pragma unroll
            for (int nf = 0; nf < 4; nf++) {
                int col = n0 + wn + nf*8 + 2*tig;
                float bx = bias[col], by = bias[col+1];
                int r0 = m0 + wm + mf*16 + grp;
                if (OUT_HALF) {
                    __half* Co = (__half*)Cout;
                    *(uint32_t*)&Co[(size_t)r0*Ndim + col] =
                        pack_h2(acc[mf][nf][0] + bx, acc[mf][nf][1] + by);
                    *(uint32_t*)&Co[(size_t)(r0+8)*Ndim + col] =
                        pack_h2(acc[mf][nf][2] + bx, acc[mf][nf][3] + by);
                } else {
                    float* Co = (float*)Cout;
                    *(float2*)&Co[(size_t)r0*Ndim + col] =
                        make_float2(acc[mf][nf][0] + bx, acc[mf][nf][1] + by);
                    *(float2*)&Co[(size_t)(r0+8)*Ndim + col] =
                        make_float2(acc[mf][nf][2] + bx, acc[mf][nf][3] + by);
                }
            }
        }
    }
}

// ---------------- fp16 tensor-core fused attention (online, max-free softmax) ----------------
// 224 threads: 7 warps x exactly 2 strips each. fp16 Q/KV in, fp16 out.
__global__ __launch_bounds__(224)
void attn_tc_kernel(const float* __restrict__ mask)
{
    extern __shared__ __half smh[];
    __half* Ksh = smh;                         // [224][40] half (K, d contiguous)
    __half* Vth = Ksh + NKP*KS_STRH;           // [32][248] half (V^T, keys contiguous)
    float*  posh = (float*)(Vth + 32*VT_STRH); // [1331]
    int*    midv = (int*)(posh + M_POS);       // [216] pid3 LUT

    int bh = blockIdx.x;
    int b  = bh / HEADS, h = bh % HEADS;
    int g  = b & (NG_-1);
    int tid = threadIdx.x;
    int w = tid >> 5, lane = tid & 31;
    int grp = lane >> 2, tig = lane & 3;

    const __half* kvbh = g_kvh + (size_t)b*NTOK*(2*CH);
    for (int e = tid; e < NKP*16; e += 224) {
        int m = e >> 4, d = (e & 15)*2;
        uint32_t ku = 0u, vu = 0u;
        if (m < NTOK) {
            ku = *(const uint32_t*)&kvbh[(size_t)m*(2*CH) + h*32 + d];
            vu = *(const uint32_t*)&kvbh[(size_t)m*(2*CH) + CH + h*32 + d];
        }
        *(uint32_t*)&Ksh[m*KS_STRH + d] = ku;
        __half2 vh = *(__half2*)&vu;
        Vth[(d    )*VT_STRH + m] = vh.x;
        Vth[(d + 1)*VT_STRH + m] = vh.y;
    }
    for (int e = tid; e < M_POS; e += 224) posh[e] = g_pos[h*M_POS + e];
    for (int e = tid; e < NTOK; e += 224)
        midv[e] = (e/36)*121 + ((e/6)%6)*11 + (e%6);
    __syncthreads();

    const float* maskb = mask + (size_t)g*NTOK*NTOK;
    const __half* qbh = g_qh + (size_t)b*NTOK*CH + h*32;
    __half* obh = g_atth + (size_t)b*NTOK*CH + h*32;
    const float scale = 0.17677669529663687f;  // 32^-0.5

    for (int strip = w; strip < MT; strip += 7) {
        int n0 = strip*16;
        int ra = n0 + grp, rb = ra + 8;
        int ra_c = min(ra, NTOK-1), rb_c = min(rb, NTOK-1);

        // Q A-frags: direct half2 loads (no cvt)
        uint32_t aq[2][4];
        const __half* qa = qbh + (size_t)ra_c*CH;
        const __half* qB = qbh + (size_t)rb_c*CH;
        #pragma unroll
        for (int c = 0; c < 2; c++) {
            aq[c][0] = *(const uint32_t*)&qa[c*16 + 2*tig];
            aq[c][1] = *(const uint32_t*)&qB[c*16 + 2*tig];
            aq[c][2] = *(const uint32_t*)&qa[c*16 + 2*tig + 8];
            aq[c][3] = *(const uint32_t*)&qB[c*16 + 2*tig + 8];
        }

        int nida = midv[ra_c], nidb = midv[rb_c];
        const float* mra = maskb + (size_t)ra_c*NTOK;
        const float* mrb = maskb + (size_t)rb_c*NTOK;

        float o[4][4];
        #pragma unroll
        for (int dt = 0; dt < 4; dt++)
            #pragma unroll
            for (int c = 0; c < 4; c++) o[dt][c] = 0.f;
        float sa = 0.f, sb = 0.f;

        // prefetched mask rows for kt=0
        int mq0 = 2*tig;
        float2 cma0 = *(const float2*)(mra + mq0);
        float2 cmb0 = *(const float2*)(mrb + mq0);
        float2 cma1 = *(const float2*)(mra + mq0 + 8);
        float2 cmb1 = *(const float2*)(mrb + mq0 + 8);

        #pragma unroll 2
        for (int kt = 0; kt < KT16; kt++) {
            // prefetch next kt's mask rows (clamped to stay in-bounds; unused values discarded)
            float2 nma0 = cma0, nmb0 = cmb0, nma1 = cma1, nmb1 = cmb1;
            if (kt + 1 < KT16) {
                int mn0 = (kt+1)*16 + 2*tig;
                int mn1 = min(mn0 + 8, NTOK - 2);
                nma0 = *(const float2*)(mra + mn0);
                nmb0 = *(const float2*)(mrb + mn0);
                nma1 = *(const float2*)(mra + mn1);
                nmb1 = *(const float2*)(mrb + mn1);
            }

            // S tiles = Q K^T
            float s0c[4] = {0.f,0.f,0.f,0.f};
            float s1c[4] = {0.f,0.f,0.f,0.f};
            int key0 = kt*16 + grp;
            #pragma unroll
            for (int c = 0; c < 2; c++) {
                uint32_t b0 = *(const uint32_t*)&Ksh[(key0    )*KS_STRH + c*16 + 2*tig];
                uint32_t b1 = *(const uint32_t*)&Ksh[(key0    )*KS_STRH + c*16 + 2*tig + 8];
                uint32_t d0 = *(const uint32_t*)&Ksh[(key0 + 8)*KS_STRH + c*16 + 2*tig];
                uint32_t d1 = *(const uint32_t*)&Ksh[(key0 + 8)*KS_STRH + c*16 + 2*tig + 8];
                asm volatile(
                    "mma.sync.aligned.m16n8k16.row.col.f32.f16.f16.f32 "
                    "{%0,%1,%2,%3}, {%4,%5,%6,%7}, {%8,%9}, {%0,%1,%2,%3};"
                    : "+f"(s0c[0]), "+f"(s0c[1]), "+f"(s0c[2]), "+f"(s0c[3])
                    : "r"(aq[c][0]), "r"(aq[c][1]), "r"(aq[c][2]), "r"(aq[c][3]),
                      "r"(b0), "r"(b1));
                asm volatile(
                    "mma.sync.aligned.m16n8k16.row.col.f32.f16.f16.f32 "
                    "{%0,%1,%2,%3}, {%4,%5,%6,%7}, {%8,%9}, {%0,%1,%2,%3};"
                    : "+f"(s1c[0]), "+f"(s1c[1]), "+f"(s1c[2]), "+f"(s1c[3])
                    : "r"(aq[c][0]), "r"(aq[c][1]), "r"(aq[c][2]), "r"(aq[c][3]),
                      "r"(d0), "r"(d1));
            }

            // bias + mask + exp, accumulate row sums, pack P A-frags directly
            uint32_t pa0, pa1, pa2, pa3;
            {
                int m0 = kt*16 + 2*tig;
                int mid0 = midv[m0], mid1 = midv[m0+1];
                float p00 = __expf(s0c[0]*scale + posh[nida - mid0 + 665] + cma0.x);
                float p01 = __expf(s0c[1]*scale + posh[nida - mid1 + 665] + cma0.y);
                float p02 = __expf(s0c[2]*scale + posh[nidb - mid0 + 665] + cmb0.x);
                float p03 = __expf(s0c[3]*scale + posh[nidb - mid1 + 665] + cmb0.y);
                sa += p00 + p01;
                sb += p02 + p03;
                pa0 = pack_h2(p00, p01);
                pa1 = pack_h2(p02, p03);
            }
            if (kt < KT16-1) {
                int m1 = kt*16 + 8 + 2*tig;
                int mid0 = midv[m1], mid1 = midv[m1+1];
                float p10 = __expf(s1c[0]*scale + posh[nida - mid0 + 665] + cma1.x);
                float p11 = __expf(s1c[1]*scale + posh[nida - mid1 + 665] + cma1.y);
                float p12 = __expf(s1c[2]*scale + posh[nidb - mid0 + 665] + cmb1.x);
                float p13 = __expf(s1c[3]*scale + posh[nidb - mid1 + 665] + cmb1.y);
                sa += p10 + p11;
                sb += p12 + p13;
                pa2 = pack_h2(p10, p11);
                pa3 = pack_h2(p12, p13);
            } else {
                pa2 = 0u; pa3 = 0u;
            }

            // O += P V
            #pragma unroll
            for (int dt = 0; dt < 4; dt++) {
                uint32_t b0 = *(const uint32_t*)&Vth[(dt*8 + grp)*VT_STRH + kt*16 + 2*tig];
                uint32_t b1 = *(const uint32_t*)&Vth[(dt*8 + grp)*VT_STRH + kt*16 + 2*tig + 8];
                asm volatile(
                    "mma.sync.aligned.m16n8k16.row.col.f32.f16.f16.f32 "
                    "{%0,%1,%2,%3}, {%4,%5,%6,%7}, {%8,%9}, {%0,%1,%2,%3};"
                    : "+f"(o[dt][0]), "+f"(o[dt][1]), "+f"(o[dt][2]), "+f"(o[dt][3])
                    : "r"(pa0), "r"(pa1), "r"(pa2), "r"(pa3),
                      "r"(b0), "r"(b1));
            }

            cma0 = nma0; cmb0 = nmb0; cma1 = nma1; cmb1 = nmb1;
        }

        sa += __shfl_xor_sync(0xffffffffu, sa, 1);
        sa += __shfl_xor_sync(0xffffffffu, sa, 2);
        sb += __shfl_xor_sync(0xffffffffu, sb, 1);
        sb += __shfl_xor_sync(0xffffffffu, sb, 2);
        float inva = 1.f / sa, invb = 1.f / sb;

        #pragma unroll
        for (int dt = 0; dt < 4; dt++) {
            int d = dt*8 + 2*tig;
            *(uint32_t*)&obh[(size_t)ra*CH + d] =
                pack_h2(o[dt][0]*inva, o[dt][1]*inva);
            if (rb < NTOK)
                *(uint32_t*)&obh[(size_t)rb*CH + d] =
                    pack_h2(o[dt][2]*invb, o[dt][3]*invb);
        }
    }
}

// ---------------- launch ----------------
extern "C" void kernel_launch(void* const* d_in, const int* in_sizes, int n_in,
                              void* d_out, int out_size)
{
    const float* x     = (const float*)d_in[0];
    const float* y     = (const float*)d_in[1];
    const float* mask  = (const float*)d_in[2];
    const float* Wqkv  = (const float*)d_in[3];
    const float* bqkv  = (const float*)d_in[4];
    const float* Wproj = (const float*)d_in[5];
    const float* bproj = (const float*)d_in[6];
    const float* ppw   = (const float*)d_in[7];
    const float* ppb   = (const float*)d_in[8];
    const float* g1    = (const float*)d_in[9];
    const float* be1   = (const float*)d_in[10];
    const float* w1    = (const float*)d_in[11];
    const float* b1    = (const float*)d_in[12];
    const float* g2    = (const float*)d_in[13];
    const float* be2   = (const float*)d_in[14];
    const float* w2    = (const float*)d_in[15];
    const float* b2    = (const float*)d_in[16];
    const float* g3    = (const float*)d_in[17];
    const float* be3   = (const float*)d_in[18];
    const float* w3    = (const float*)d_in[19];
    const float* b3    = (const float*)d_in[20];
    float* out = (float*)d_out;

    __half *qp, *kvp, *attp;
    cudaGetSymbolAddress((void**)&qp,   g_qh);
    cudaGetSymbolAddress((void**)&kvp,  g_kvh);
    cudaGetSymbolAddress((void**)&attp, g_atth);

    pos_mlp_kernel<<<(M_POS+255)/256, 256>>>(ppw, ppb, g1, be1, w1, b1,
                                             g2, be2, w2, b2, g3, be3, w3, b3);
    cudaFuncSetAttribute(gemm_f16_big<false,true>,
                         cudaFuncAttributeMaxDynamicSharedMemorySize, GSMEM);
    cudaFuncSetAttribute(gemm_f16_big<true,false>,
                         cudaFuncAttributeMaxDynamicSharedMemorySize, GSMEM);

    // Q = x @ Wq^T + bq  -> half
    gemm_f16_big<false,true><<<MROWS/128, 256, GSMEM>>>(x, Wqkv, bqkv, qp, CH);
    // KV = y @ Wkv^T + bkv -> half
    gemm_f16_big<false,true><<<MROWS/128, 256, GSMEM>>>(y, Wqkv + (size_t)CH*CH,
                                                        bqkv + CH, kvp, 2*CH);
    // fused attention (half in, half out)
    {
        size_t smem = (size_t)(NKP*KS_STRH + 32*VT_STRH)*2 + (size_t)(M_POS + NTOK)*4;
        cudaFuncSetAttribute(attn_tc_kernel, cudaFuncAttributeMaxDynamicSharedMemorySize, (int)smem);
        attn_tc_kernel<<<B_*HEADS, 224, smem>>>(mask);
    }
    // out = att @ Wproj^T + bproj  (half A, float out)
    gemm_f16_big<true,false><<<MROWS/128, 256, GSMEM>>>(attp, Wproj, bproj, out, CH);
}

// round 12
// speedup vs baseline: 6.1934x; 1.0699x over previous
#include <cuda_runtime.h>
#include <cuda_fp16.h>
#include <math.h>
#include <stdint.h>

#define B_     256
#define NG_    64
#define HEADS  6
#define CH     192
#define NTOK   216
#define HD     32
#define M_POS  1331
#define PDIM   12
#define MROWS  (B_*NTOK)   // 55296

// fp16 attention tiling
#define NKP     224        // keys padded to 14*16
#define KS_STRH 40         // K smem row stride in halves: conflict-free frag loads
#define VT_STRH 248        // V^T smem row stride in halves: conflict-free frag loads
#define KT16    14         // 16-key tiles
#define MT      14         // m16 query strips

// fp16 GEMM (A-resident) tiling
#define AHS     200        // A smem row stride in halves (banks 4*grp+tig, conflict-free)
#define WSTH    40         // W stage row stride in halves (k32 stage)
#define GSMEM   ((128*AHS + 2*64*WSTH)*2)   // 61440 B

// ---------------- scratch (all intermediates fp16) ----------------
__device__ __half g_qh  [(size_t)MROWS*CH];
__device__ __half g_kvh [(size_t)MROWS*2*CH];
__device__ __half g_atth[(size_t)MROWS*CH];
__device__ __half g_wh  [(size_t)4*CH*CH];     // [Wqkv(3C) ; Wproj(C)] rows, half
__device__ float  g_pos [HEADS*M_POS];

__device__ __forceinline__ uint32_t pack_h2(float a, float b) {
    __half2 h = __floats2half2_rn(a, b);
    return *(uint32_t*)&h;
}

// ---------------- tiny dynamic position-bias MLP ----------------
__device__ __forceinline__ void ln12(float* t, const float* g, const float* b) {
    float mu = 0.f;
    #pragma unroll
    for (int i = 0; i < PDIM; i++) mu += t[i];
    mu *= (1.f/PDIM);
    float v = 0.f;
    #pragma unroll
    for (int i = 0; i < PDIM; i++) { float d = t[i]-mu; v += d*d; }
    v *= (1.f/PDIM);
    float inv = rsqrtf(v + 1e-5f);
    #pragma unroll
    for (int i = 0; i < PDIM; i++) t[i] = (t[i]-mu)*inv*g[i] + b[i];
}

__global__ void pos_mlp_kernel(
    const float* __restrict__ ppw, const float* __restrict__ ppb,
    const float* __restrict__ g1,  const float* __restrict__ be1,
    const float* __restrict__ w1,  const float* __restrict__ b1,
    const float* __restrict__ g2,  const float* __restrict__ be2,
    const float* __restrict__ w2,  const float* __restrict__ b2,
    const float* __restrict__ g3,  const float* __restrict__ be3,
    const float* __restrict__ w3,  const float* __restrict__ b3)
{
    int m = blockIdx.x*blockDim.x + threadIdx.x;
    if (m >= M_POS) return;
    float c0 = (float)(m/121 - 5);
    float c1 = (float)((m/11)%11 - 5);
    float c2 = (float)(m%11 - 5);
    float t[PDIM], u[PDIM];
    #pragma unroll
    for (int i = 0; i < PDIM; i++)
        t[i] = ppw[i*3+0]*c0 + ppw[i*3+1]*c1 + ppw[i*3+2]*c2 + ppb[i];
    ln12(t, g1, be1);
    #pragma unroll
    for (int i = 0; i < PDIM; i++) {
        float acc = b1[i];
        #pragma unroll
        for (int j = 0; j < PDIM; j++) acc += w1[i*PDIM+j]*fmaxf(t[j],0.f);
        u[i] = acc;
    }
    ln12(u, g2, be2);
    #pragma unroll
    for (int i = 0; i < PDIM; i++) {
        float acc = b2[i];
        #pragma unroll
        for (int j = 0; j < PDIM; j++) acc += w2[i*PDIM+j]*fmaxf(u[j],0.f);
        t[i] = acc;
    }
    ln12(t, g3, be3);
    #pragma unroll
    for (int h = 0; h < HEADS; h++) {
        float acc = b3[h];
        #pragma unroll
        for (int j = 0; j < PDIM; j++) acc += w3[h*PDIM+j]*fmaxf(t[j],0.f);
        g_pos[h*M_POS + m] = acc;
    }
}

// ---------------- one-shot weight conversion fp32 -> fp16 ----------------
__global__ void conv_w_kernel(const float* __restrict__ Wqkv,
                              const float* __restrict__ Wproj)
{
    int i = (blockIdx.x*256 + threadIdx.x) * 4;
    const int QKV = 3*CH*CH;
    const int TOT = 4*CH*CH;
    if (i >= TOT) return;
    float4 v = (i < QKV) ? *(const float4*)(Wqkv + i)
                         : *(const float4*)(Wproj + (i - QKV));
    uint2 p = make_uint2(pack_h2(v.x, v.y), pack_h2(v.z, v.w));
    *(uint2*)&g_wh[i] = p;
}

// ---------------- FP16 tensor-core GEMM, A-resident, k32 stages, half W ----------------
// C[m][n] = sum_k A[m][k]*Wh[n][k] + bias[n].  One CTA owns 128 rows, loops N/64 blocks.
template<bool A_HALF, bool OUT_HALF>
__global__ __launch_bounds__(256)
void gemm_f16_big(const void* __restrict__ Ain, const __half* __restrict__ Wh,
                  const float* __restrict__ bias, void* __restrict__ Cout, int Ndim)
{
    extern __shared__ __half sg[];
    __half* Ah  = sg;                 // [128][AHS]
    __half* Wst = Ah + 128*AHS;       // [2][64][WSTH]

    int tid  = threadIdx.x;
    int w    = tid >> 5, lane = tid & 31;
    int grp  = lane >> 2, tig = lane & 3;
    int wm   = (w >> 1) * 32;
    int wn   = (w & 1) * 32;
    int m0   = blockIdx.x * 128;

    // load entire A stripe (128 x 192) into SMEM as half
    if (A_HALF) {
        const __half* Af = (const __half*)Ain + (size_t)m0*CH;
        #pragma unroll
        for (int i = 0; i < 24; i++) {
            int idx = i*256 + tid;
            int row = idx/48, c4 = idx%48;
            uint2 v = *(const uint2*)(Af + (size_t)row*CH + c4*4);
            *(uint2*)&Ah[row*AHS + c4*4] = v;
        }
    } else {
        const float* Af = (const float*)Ain + (size_t)m0*CH;
        #pragma unroll
        for (int i = 0; i < 24; i++) {
            int idx = i*256 + tid;
            int row = idx/48, c4 = idx%48;
            float4 v = *(const float4*)(Af + (size_t)row*CH + c4*4);
            uint2 p = make_uint2(pack_h2(v.x, v.y), pack_h2(v.z, v.w));
            *(uint2*)&Ah[row*AHS + c4*4] = p;
        }
    }
    __syncthreads();

    int wrow = tid >> 2;            // 0..63
    int wk8  = (tid & 3) * 8;       // 0,8,16,24 halves
    const uint32_t* Ahw = (const uint32_t*)Ah;
    int nbc = Ndim >> 6;

    for (int nb = 0; nb < nbc; nb++) {
        int n0 = nb*64;
        const __half* Wb = Wh + (size_t)(n0 + wrow)*CH + wk8;
        uint4 wR = *(const uint4*)Wb;

        float acc[2][4][4];
        #pragma unroll
        for (int i = 0; i < 2; i++)
            #pragma unroll
            for (int j = 0; j < 4; j++)
                #pragma unroll
                for (int c = 0; c < 4; c++) acc[i][j][c] = 0.f;

        #pragma unroll
        for (int st = 0; st < 6; st++) {       // k32 per stage
            uint32_t* Wsw = (uint32_t*)(Wst + (st & 1)*64*WSTH);
            *(uint4*)&Wsw[wrow*(WSTH/2) + (tid & 3)*4] = wR;
            __syncthreads();
            if (st < 5) wR = *(const uint4*)(Wb + (st+1)*32);

            #pragma unroll
            for (int c = 0; c < 2; c++) {      // two k16 halves of the stage
                int ko = st*16 + c*8;          // word offset into A rows
                uint32_t af[2][4], bf[4][2];
                #pragma unroll
                for (int mf = 0; mf < 2; mf++) {
                    int r = wm + mf*16 + grp;
                    af[mf][0] = Ahw[(r    )*(AHS/2) + ko + tig];
                    af[mf][1] = Ahw[(r + 8)*(AHS/2) + ko + tig];
                    af[mf][2] = Ahw[(r    )*(AHS/2) + ko + tig + 4];
                    af[mf][3] = Ahw[(r + 8)*(AHS/2) + ko + tig + 4];
                }
                #pragma unroll
                for (int nf = 0; nf < 4; nf++) {
                    int n = wn + nf*8 + grp;
                    bf[nf][0] = Wsw[n*(WSTH/2) + c*8 + tig];
                    bf[nf][1] = Wsw[n*(WSTH/2) + c*8 + tig + 4];
                }
                #pragma unroll
                for (int mf = 0; mf < 2; mf++)
                    #pragma unroll
                    for (int nf = 0; nf < 4; nf++) {
                        asm volatile(
                            "mma.sync.aligned.m16n8k16.row.col.f32.f16.f16.f32 "
                            "{%0,%1,%2,%3}, {%4,%5,%6,%7}, {%8,%9}, {%0,%1,%2,%3};"
                            : "+f"(acc[mf][nf][0]), "+f"(acc[mf][nf][1]),
                              "+f"(acc[mf][nf][2]), "+f"(acc[mf][nf][3])
                            : "r"(af[mf][0]), "r"(af[mf][1]), "r"(af[mf][2]), "r"(af[mf][3]),
                              "r"(bf[nf][0]), "r"(bf[nf][1]));
                    }
            }
        }

        // epilogue for this n-block
        #pragma unroll
        for (int mf = 0; mf < 2; mf++) {
            #pragma unroll
            for (int nf = 0; nf < 4; nf++) {
                int col = n0 + wn + nf*8 + 2*tig;
                float bx = bias[col], by = bias[col+1];
                int r0 = m0 + wm + mf*16 + grp;
                if (OUT_HALF) {
                    __half* Co = (__half*)Cout;
                    *(uint32_t*)&Co[(size_t)r0*Ndim + col] =
                        pack_h2(acc[mf][nf][0] + bx, acc[mf][nf][1] + by);
                    *(uint32_t*)&Co[(size_t)(r0+8)*Ndim + col] =
                        pack_h2(acc[mf][nf][2] + bx, acc[mf][nf][3] + by);
                } else {
                    float* Co = (float*)Cout;
                    *(float2*)&Co[(size_t)r0*Ndim + col] =
                        make_float2(acc[mf][nf][0] + bx, acc[mf][nf][1] + by);
                    *(float2*)&Co[(size_t)(r0+8)*Ndim + col] =
                        make_float2(acc[mf][nf][2] + bx, acc[mf][nf][3] + by);
                }
            }
        }
        __syncthreads();   // protect W stage buffers before next n-block
    }
}

// ---------------- fp16 tensor-core fused attention (online, max-free softmax) ----------------
// 224 threads: 7 warps x exactly 2 strips. Paired pos-bias LUT (float2 per LDS.64).
__global__ __launch_bounds__(224)
void attn_tc_kernel(const float* __restrict__ mask)
{
    extern __shared__ __half smh[];
    __half* Ksh  = smh;                          // [224][40] half
    __half* Vth  = Ksh + NKP*KS_STRH;            // [32][248] half (V^T)
    float2* poshd = (float2*)(Vth + 32*VT_STRH); // [1331] (pos[a], pos[a-1])
    short*  midv  = (short*)(poshd + M_POS);     // [216] pid3 LUT

    int bh = blockIdx.x;
    int b  = bh / HEADS, h = bh % HEADS;
    int g  = b & (NG_-1);
    int tid = threadIdx.x;
    int w = tid >> 5, lane = tid & 31;
    int grp = lane >> 2, tig = lane & 3;

    const __half* kvbh = g_kvh + (size_t)b*NTOK*(2*CH);
    for (int e = tid; e < NKP*16; e += 224) {
        int m = e >> 4, d = (e & 15)*2;
        uint32_t ku = 0u, vu = 0u;
        if (m < NTOK) {
            ku = *(const uint32_t*)&kvbh[(size_t)m*(2*CH) + h*32 + d];
            vu = *(const uint32_t*)&kvbh[(size_t)m*(2*CH) + CH + h*32 + d];
        }
        *(uint32_t*)&Ksh[m*KS_STRH + d] = ku;
        __half2 vh = *(__half2*)&vu;
        Vth[(d    )*VT_STRH + m] = vh.x;
        Vth[(d + 1)*VT_STRH + m] = vh.y;
    }
    for (int e = tid; e < M_POS; e += 224) {
        float cur = g_pos[h*M_POS + e];
        float prv = (e > 0) ? g_pos[h*M_POS + e - 1] : 0.f;
        poshd[e] = make_float2(cur, prv);
    }
    for (int e = tid; e < NTOK; e += 224)
        midv[e] = (short)((e/36)*121 + ((e/6)%6)*11 + (e%6));
    __syncthreads();

    const float* maskb = mask + (size_t)g*NTOK*NTOK;
    const __half* qbh = g_qh + (size_t)b*NTOK*CH + h*32;
    __half* obh = g_atth + (size_t)b*NTOK*CH + h*32;
    const float scale = 0.17677669529663687f;  // 32^-0.5

    for (int strip = w; strip < MT; strip += 7) {
        int n0 = strip*16;
        int ra = n0 + grp, rb = ra + 8;
        int ra_c = min(ra, NTOK-1), rb_c = min(rb, NTOK-1);

        // Q A-frags: direct half2 loads
        uint32_t aq[2][4];
        const __half* qa = qbh + (size_t)ra_c*CH;
        const __half* qB = qbh + (size_t)rb_c*CH;
        #pragma unroll
        for (int c = 0; c < 2; c++) {
            aq[c][0] = *(const uint32_t*)&qa[c*16 + 2*tig];
            aq[c][1] = *(const uint32_t*)&qB[c*16 + 2*tig];
            aq[c][2] = *(const uint32_t*)&qa[c*16 + 2*tig + 8];
            aq[c][3] = *(const uint32_t*)&qB[c*16 + 2*tig + 8];
        }

        int nida = midv[ra_c], nidb = midv[rb_c];
        const float* mra = maskb + (size_t)ra_c*NTOK;
        const float* mrb = maskb + (size_t)rb_c*NTOK;

        float o[4][4];
        #pragma unroll
        for (int dt = 0; dt < 4; dt++)
            #pragma unroll
            for (int c = 0; c < 4; c++) o[dt][c] = 0.f;
        float sa = 0.f, sb = 0.f;

        // prefetched mask rows for kt=0
        int mq0 = 2*tig;
        float2 cma0 = *(const float2*)(mra + mq0);
        float2 cmb0 = *(const float2*)(mrb + mq0);
        float2 cma1 = *(const float2*)(mra + mq0 + 8);
        float2 cmb1 = *(const float2*)(mrb + mq0 + 8);

        #pragma unroll 2
        for (int kt = 0; kt < KT16; kt++) {
            // prefetch next kt's mask rows
            float2 nma0 = cma0, nmb0 = cmb0, nma1 = cma1, nmb1 = cmb1;
            if (kt + 1 < KT16) {
                int mn0 = (kt+1)*16 + 2*tig;
                int mn1 = min(mn0 + 8, NTOK - 2);
                nma0 = *(const float2*)(mra + mn0);
                nmb0 = *(const float2*)(mrb + mn0);
                nma1 = *(const float2*)(mra + mn1);
                nmb1 = *(const float2*)(mrb + mn1);
            }

            // S tiles = Q K^T
            float s0c[4] = {0.f,0.f,0.f,0.f};
            float s1c[4] = {0.f,0.f,0.f,0.f};
            int key0 = kt*16 + grp;
            #pragma unroll
            for (int c = 0; c < 2; c++) {
                uint32_t b0 = *(const uint32_t*)&Ksh[(key0    )*KS_STRH + c*16 + 2*tig];
                uint32_t b1 = *(const uint32_t*)&Ksh[(key0    )*KS_STRH + c*16 + 2*tig + 8];
                uint32_t d0 = *(const uint32_t*)&Ksh[(key0 + 8)*KS_STRH + c*16 + 2*tig];
                uint32_t d1 = *(const uint32_t*)&Ksh[(key0 + 8)*KS_STRH + c*16 + 2*tig + 8];
                asm volatile(
                    "mma.sync.aligned.m16n8k16.row.col.f32.f16.f16.f32 "
                    "{%0,%1,%2,%3}, {%4,%5,%6,%7}, {%8,%9}, {%0,%1,%2,%3};"
                    : "+f"(s0c[0]), "+f"(s0c[1]), "+f"(s0c[2]), "+f"(s0c[3])
                    : "r"(aq[c][0]), "r"(aq[c][1]), "r"(aq[c][2]), "r"(aq[c][3]),
                      "r"(b0), "r"(b1));
                asm volatile(
                    "mma.sync.aligned.m16n8k16.row.col.f32.f16.f16.f32 "
                    "{%0,%1,%2,%3}, {%4,%5,%6,%7}, {%8,%9}, {%0,%1,%2,%3};"
                    : "+f"(s1c[0]), "+f"(s1c[1]), "+f"(s1c[2]), "+f"(s1c[3])
                    : "r"(aq[c][0]), "r"(aq[c][1]), "r"(aq[c][2]), "r"(aq[c][3]),
                      "r"(d0), "r"(d1));
            }

            // bias(paired LUT) + mask + exp, accumulate row sums, pack P frags
            uint32_t pa0, pa1, pa2, pa3;
            {
                int m0 = kt*16 + 2*tig;
                int mid0 = midv[m0];
                float2 Pa = poshd[nida - mid0 + 665];   // .x even m, .y odd m
                float2 Pb = poshd[nidb - mid0 + 665];
                float p00 = __expf(s0c[0]*scale + Pa.x + cma0.x);
                float p01 = __expf(s0c[1]*scale + Pa.y + cma0.y);
                float p02 = __expf(s0c[2]*scale + Pb.x + cmb0.x);
                float p03 = __expf(s0c[3]*scale + Pb.y + cmb0.y);
                sa += p00 + p01;
                sb += p02 + p03;
                pa0 = pack_h2(p00, p01);
                pa1 = pack_h2(p02, p03);
            }
            if (kt < KT16-1) {
                int m1 = kt*16 + 8 + 2*tig;
                int mid1 = midv[m1];
                float2 Pa = poshd[nida - mid1 + 665];
                float2 Pb = poshd[nidb - mid1 + 665];
                float p10 = __expf(s1c[0]*scale + Pa.x + cma1.x);
                float p11 = __expf(s1c[1]*scale + Pa.y + cma1.y);
                float p12 = __expf(s1c[2]*scale + Pb.x + cmb1.x);
                float p13 = __expf(s1c[3]*scale + Pb.y + cmb1.y);
                sa += p10 + p11;
                sb += p12 + p13;
                pa2 = pack_h2(p10, p11);
                pa3 = pack_h2(p12, p13);
            } else {
                pa2 = 0u; pa3 = 0u;
            }

            // O += P V
            #pragma unroll
            for (int dt = 0; dt < 4; dt++) {
                uint32_t b0 = *(const uint32_t*)&Vth[(dt*8 + grp)*VT_STRH + kt*16 + 2*tig];
                uint32_t b1 = *(const uint32_t*)&Vth[(dt*8 + grp)*VT_STRH + kt*16 + 2*tig + 8];
                asm volatile(
                    "mma.sync.aligned.m16n8k16.row.col.f32.f16.f16.f32 "
                    "{%0,%1,%2,%3}, {%4,%5,%6,%7}, {%8,%9}, {%0,%1,%2,%3};"
                    : "+f"(o[dt][0]), "+f"(o[dt][1]), "+f"(o[dt][2]), "+f"(o[dt][3])
                    : "r"(pa0), "r"(pa1), "r"(pa2), "r"(pa3),
                      "r"(b0), "r"(b1));
            }

            cma0 = nma0; cmb0 = nmb0; cma1 = nma1; cmb1 = nmb1;
        }

        sa += __shfl_xor_sync(0xffffffffu, sa, 1);
        sa += __shfl_xor_sync(0xffffffffu, sa, 2);
        sb += __shfl_xor_sync(0xffffffffu, sb, 1);
        sb += __shfl_xor_sync(0xffffffffu, sb, 2);
        float inva = 1.f / sa, invb = 1.f / sb;

        #pragma unroll
        for (int dt = 0; dt < 4; dt++) {
            int d = dt*8 + 2*tig;
            *(uint32_t*)&obh[(size_t)ra*CH + d] =
                pack_h2(o[dt][0]*inva, o[dt][1]*inva);
            if (rb < NTOK)
                *(uint32_t*)&obh[(size_t)rb*CH + d] =
                    pack_h2(o[dt][2]*invb, o[dt][3]*invb);
        }
    }
}

// ---------------- launch ----------------
extern "C" void kernel_launch(void* const* d_in, const int* in_sizes, int n_in,
                              void* d_out, int out_size)
{
    const float* x     = (const float*)d_in[0];
    const float* y     = (const float*)d_in[1];
    const float* mask  = (const float*)d_in[2];
    const float* Wqkv  = (const float*)d_in[3];
    const float* bqkv  = (const float*)d_in[4];
    const float* Wproj = (const float*)d_in[5];
    const float* bproj = (const float*)d_in[6];
    const float* ppw   = (const float*)d_in[7];
    const float* ppb   = (const float*)d_in[8];
    const float* g1    = (const float*)d_in[9];
    const float* be1   = (const float*)d_in[10];
    const float* w1    = (const float*)d_in[11];
    const float* b1    = (const float*)d_in[12];
    const float* g2    = (const float*)d_in[13];
    const float* be2   = (const float*)d_in[14];
    const float* w2    = (const float*)d_in[15];
    const float* b2    = (const float*)d_in[16];
    const float* g3    = (const float*)d_in[17];
    const float* be3   = (const float*)d_in[18];
    const float* w3    = (const float*)d_in[19];
    const float* b3    = (const float*)d_in[20];
    float* out = (float*)d_out;

    __half *qp, *kvp, *attp, *whp;
    cudaGetSymbolAddress((void**)&qp,   g_qh);
    cudaGetSymbolAddress((void**)&kvp,  g_kvh);
    cudaGetSymbolAddress((void**)&attp, g_atth);
    cudaGetSymbolAddress((void**)&whp,  g_wh);

    pos_mlp_kernel<<<(M_POS+255)/256, 256>>>(ppw, ppb, g1, be1, w1, b1,
                                             g2, be2, w2, b2, g3, be3, w3, b3);
    conv_w_kernel<<<(4*CH*CH/4 + 255)/256, 256>>>(Wqkv, Wproj);

    cudaFuncSetAttribute(gemm_f16_big<false,true>,
                         cudaFuncAttributeMaxDynamicSharedMemorySize, GSMEM);
    cudaFuncSetAttribute(gemm_f16_big<true,false>,
                         cudaFuncAttributeMaxDynamicSharedMemorySize, GSMEM);

    // Q = x @ Wq^T + bq  -> half
    gemm_f16_big<false,true><<<MROWS/128, 256, GSMEM>>>(x, whp, bqkv, qp, CH);
    // KV = y @ Wkv^T + bkv -> half
    gemm_f16_big<false,true><<<MROWS/128, 256, GSMEM>>>(y, whp + (size_t)CH*CH,
                                                        bqkv + CH, kvp, 2*CH);
    // fused attention (half in, half out)
    {
        size_t smem = (size_t)(NKP*KS_STRH + 32*VT_STRH)*2
                    + (size_t)M_POS*8 + (size_t)NTOK*2;
        cudaFuncSetAttribute(attn_tc_kernel, cudaFuncAttributeMaxDynamicSharedMemorySize, (int)smem);
        attn_tc_kernel<<<B_*HEADS, 224, smem>>>(mask);
    }
    // out = att @ Wproj^T + bproj  (half A, float out)
    gemm_f16_big<true,false><<<MROWS/128, 256, GSMEM>>>(attp, whp + (size_t)3*CH*CH,
                                                        bproj, out, CH);
}

// round 13
// speedup vs baseline: 6.7490x; 1.0897x over previous
#include <cuda_runtime.h>
#include <cuda_fp16.h>
#include <math.h>
#include <stdint.h>

#define B_     256
#define NG_    64
#define HEADS  6
#define CH     192
#define NTOK   216
#define HD     32
#define M_POS  1331
#define PDIM   12
#define MROWS  (B_*NTOK)   // 55296

// fp16 attention tiling
#define NKP     224        // keys padded to 14*16
#define KS_STRH 40         // K smem row stride in halves: conflict-free frag loads
#define VT_STRH 248        // V^T smem row stride in halves: conflict-free frag loads
#define KT16    14         // 16-key tiles
#define MT      14         // m16 query strips

// fp16 GEMM (A-resident, whole-W-block) tiling
#define AHS     200        // SMEM row stride in halves (banks 4*grp+tig, conflict-free)
#define GSMEM   ((128*AHS + 64*AHS)*2)   // 76800 B

// ---------------- scratch (all intermediates fp16) ----------------
__device__ __half   g_qh   [(size_t)MROWS*CH];
__device__ __half   g_kvh  [(size_t)MROWS*2*CH];
__device__ __half   g_atth [(size_t)MROWS*CH];
__device__ __half   g_wh   [(size_t)4*CH*CH];     // [Wqkv(3C) ; Wproj(C)] rows, half
__device__ float    g_pos  [HEADS*M_POS];
__device__ uint32_t g_mbits[(size_t)NG_*NTOK*8];  // mask bitmask: 1 = masked

__device__ __forceinline__ uint32_t pack_h2(float a, float b) {
    __half2 h = __floats2half2_rn(a, b);
    return *(uint32_t*)&h;
}

// ---------------- tiny dynamic position-bias MLP ----------------
__device__ __forceinline__ void ln12(float* t, const float* g, const float* b) {
    float mu = 0.f;
    #pragma unroll
    for (int i = 0; i < PDIM; i++) mu += t[i];
    mu *= (1.f/PDIM);
    float v = 0.f;
    #pragma unroll
    for (int i = 0; i < PDIM; i++) { float d = t[i]-mu; v += d*d; }
    v *= (1.f/PDIM);
    float inv = rsqrtf(v + 1e-5f);
    #pragma unroll
    for (int i = 0; i < PDIM; i++) t[i] = (t[i]-mu)*inv*g[i] + b[i];
}

__global__ void pos_mlp_kernel(
    const float* __restrict__ ppw, const float* __restrict__ ppb,
    const float* __restrict__ g1,  const float* __restrict__ be1,
    const float* __restrict__ w1,  const float* __restrict__ b1,
    const float* __restrict__ g2,  const float* __restrict__ be2,
    const float* __restrict__ w2,  const float* __restrict__ b2,
    const float* __restrict__ g3,  const float* __restrict__ be3,
    const float* __restrict__ w3,  const float* __restrict__ b3)
{
    int m = blockIdx.x*blockDim.x + threadIdx.x;
    if (m >= M_POS) return;
    float c0 = (float)(m/121 - 5);
    float c1 = (float)((m/11)%11 - 5);
    float c2 = (float)(m%11 - 5);
    float t[PDIM], u[PDIM];
    #pragma unroll
    for (int i = 0; i < PDIM; i++)
        t[i] = ppw[i*3+0]*c0 + ppw[i*3+1]*c1 + ppw[i*3+2]*c2 + ppb[i];
    ln12(t, g1, be1);
    #pragma unroll
    for (int i = 0; i < PDIM; i++) {
        float acc = b1[i];
        #pragma unroll
        for (int j = 0; j < PDIM; j++) acc += w1[i*PDIM+j]*fmaxf(t[j],0.f);
        u[i] = acc;
    }
    ln12(u, g2, be2);
    #pragma unroll
    for (int i = 0; i < PDIM; i++) {
        float acc = b2[i];
        #pragma unroll
        for (int j = 0; j < PDIM; j++) acc += w2[i*PDIM+j]*fmaxf(u[j],0.f);
        t[i] = acc;
    }
    ln12(t, g3, be3);
    #pragma unroll
    for (int h = 0; h < HEADS; h++) {
        float acc = b3[h];
        #pragma unroll
        for (int j = 0; j < PDIM; j++) acc += w3[h*PDIM+j]*fmaxf(t[j],0.f);
        g_pos[h*M_POS + m] = acc;
    }
}

// ---------------- one-shot weight conversion fp32 -> fp16 ----------------
__global__ void conv_w_kernel(const float* __restrict__ Wqkv,
                              const float* __restrict__ Wproj)
{
    int i = (blockIdx.x*256 + threadIdx.x) * 4;
    const int QKV = 3*CH*CH;
    const int TOT = 4*CH*CH;
    if (i >= TOT) return;
    float4 v = (i < QKV) ? *(const float4*)(Wqkv + i)
                         : *(const float4*)(Wproj + (i - QKV));
    uint2 p = make_uint2(pack_h2(v.x, v.y), pack_h2(v.z, v.w));
    *(uint2*)&g_wh[i] = p;
}

// ---------------- one-shot mask -> bitmask ----------------
__global__ void mask_bits_kernel(const float* __restrict__ mask)
{
    int row  = (blockIdx.x*256 + threadIdx.x) >> 5;   // g*NTOK + n
    int lane = threadIdx.x & 31;
    if (row >= NG_*NTOK) return;
    const float* r = mask + (size_t)row*NTOK;
    #pragma unroll
    for (int i = 0; i < 7; i++) {
        int m = i*32 + lane;
        bool bit = (m < NTOK) && (r[m] < -1.f);
        uint32_t wv = __ballot_sync(0xffffffffu, bit);
        if (lane == 0) g_mbits[(size_t)row*8 + i] = wv;
    }
}

// ---------------- FP16 tensor-core GEMM: A-resident, whole-W-block, reg prefetch ----------------
// C[m][n] = sum_k A[m][k]*Wh[n][k] + bias[n].  One CTA owns 128 rows, loops N/64 blocks.
template<bool A_HALF, bool OUT_HALF>
__global__ __launch_bounds__(256)
void gemm_f16_big(const void* __restrict__ Ain, const __half* __restrict__ Wh,
                  const float* __restrict__ bias, void* __restrict__ Cout, int Ndim)
{
    extern __shared__ __half sg[];
    __half* Ah = sg;                 // [128][AHS]
    __half* Ws = Ah + 128*AHS;       // [64][AHS]

    int tid  = threadIdx.x;
    int w    = tid >> 5, lane = tid & 31;
    int grp  = lane >> 2, tig = lane & 3;
    int wm   = (w >> 1) * 32;
    int wn   = (w & 1) * 32;
    int m0   = blockIdx.x * 128;

    // load entire A stripe (128 x 192) into SMEM as half
    if (A_HALF) {
        const __half* Af = (const __half*)Ain + (size_t)m0*CH;
        #pragma unroll
        for (int i = 0; i < 24; i++) {
            int idx = i*256 + tid;
            int row = idx/48, c4 = idx%48;
            uint2 v = *(const uint2*)(Af + (size_t)row*CH + c4*4);
            *(uint2*)&Ah[row*AHS + c4*4] = v;
        }
    } else {
        const float* Af = (const float*)Ain + (size_t)m0*CH;
        #pragma unroll
        for (int i = 0; i < 24; i++) {
            int idx = i*256 + tid;
            int row = idx/48, c4 = idx%48;
            float4 v = *(const float4*)(Af + (size_t)row*CH + c4*4);
            uint2 p = make_uint2(pack_h2(v.x, v.y), pack_h2(v.z, v.w));
            *(uint2*)&Ah[row*AHS + c4*4] = p;
        }
    }

    // W-block load mapping: 64 rows x 192 halves = 1536 uint4; 6 per thread
    int wrow = tid / 24 + 0;                 // via idx below
    const uint32_t* Ahw = (const uint32_t*)Ah;
    uint32_t* Wsw = (uint32_t*)Ws;
    int nbc = Ndim >> 6;

    // prefetch W block 0
    uint4 wR[6];
    #pragma unroll
    for (int i = 0; i < 6; i++) {
        int idx = i*256 + tid;
        int row = idx/24, c8 = idx%24;
        wR[i] = *(const uint4*)(Wh + (size_t)row*CH + c8*8);
    }

    for (int nb = 0; nb < nbc; nb++) {
        // store W block to SMEM
        #pragma unroll
        for (int i = 0; i < 6; i++) {
            int idx = i*256 + tid;
            int row = idx/24, c8 = idx%24;
            *(uint4*)&Ws[row*AHS + c8*8] = wR[i];
        }
        __syncthreads();

        // prefetch next W block into registers (consumed after MMAs)
        if (nb + 1 < nbc) {
            const __half* Wb = Wh + (size_t)(nb+1)*64*CH;
            #pragma unroll
            for (int i = 0; i < 6; i++) {
                int idx = i*256 + tid;
                int row = idx/24, c8 = idx%24;
                wR[i] = *(const uint4*)(Wb + (size_t)row*CH + c8*8);
            }
        }

        float acc[2][4][4];
        #pragma unroll
        for (int i = 0; i < 2; i++)
            #pragma unroll
            for (int j = 0; j < 4; j++)
                #pragma unroll
                for (int c = 0; c < 4; c++) acc[i][j][c] = 0.f;

        // 12 uninterrupted k16 steps
        #pragma unroll
        for (int st = 0; st < 12; st++) {
            int ko = st*8;
            uint32_t af[2][4], bf[4][2];
            #pragma unroll
            for (int mf = 0; mf < 2; mf++) {
                int r = wm + mf*16 + grp;
                af[mf][0] = Ahw[(r    )*(AHS/2) + ko + tig];
                af[mf][1] = Ahw[(r + 8)*(AHS/2) + ko + tig];
                af[mf][2] = Ahw[(r    )*(AHS/2) + ko + tig + 4];
                af[mf][3] = Ahw[(r + 8)*(AHS/2) + ko + tig + 4];
            }
            #pragma unroll
            for (int nf = 0; nf < 4; nf++) {
                int n = wn + nf*8 + grp;
                bf[nf][0] = Wsw[n*(AHS/2) + ko + tig];
                bf[nf][1] = Wsw[n*(AHS/2) + ko + tig + 4];
            }
            #pragma unroll
            for (int mf = 0; mf < 2; mf++)
                #pragma unroll
                for (int nf = 0; nf < 4; nf++) {
                    asm volatile(
                        "mma.sync.aligned.m16n8k16.row.col.f32.f16.f16.f32 "
                        "{%0,%1,%2,%3}, {%4,%5,%6,%7}, {%8,%9}, {%0,%1,%2,%3};"
                        : "+f"(acc[mf][nf][0]), "+f"(acc[mf][nf][1]),
                          "+f"(acc[mf][nf][2]), "+f"(acc[mf][nf][3])
                        : "r"(af[mf][0]), "r"(af[mf][1]), "r"(af[mf][2]), "r"(af[mf][3]),
                          "r"(bf[nf][0]), "r"(bf[nf][1]));
                }
        }

        // epilogue
        int n0 = nb*64;
        #pragma unroll
        for (int mf = 0; mf < 2; mf++) {
            #pragma unroll
            for (int nf = 0; nf < 4; nf++) {
                int col = n0 + wn + nf*8 + 2*tig;
                float bx = bias[col], by = bias[col+1];
                int r0 = m0 + wm + mf*16 + grp;
                if (OUT_HALF) {
                    __half* Co = (__half*)Cout;
                    *(uint32_t*)&Co[(size_t)r0*Ndim + col] =
                        pack_h2(acc[mf][nf][0] + bx, acc[mf][nf][1] + by);
                    *(uint32_t*)&Co[(size_t)(r0+8)*Ndim + col] =
                        pack_h2(acc[mf][nf][2] + bx, acc[mf][nf][3] + by);
                } else {
                    float* Co = (float*)Cout;
                    *(float2*)&Co[(size_t)r0*Ndim + col] =
                        make_float2(acc[mf][nf][0] + bx, acc[mf][nf][1] + by);
                    *(float2*)&Co[(size_t)(r0+8)*Ndim + col] =
                        make_float2(acc[mf][nf][2] + bx, acc[mf][nf][3] + by);
                }
            }
        }
        __syncthreads();   // protect Ws before next block's store
    }
}

// ---------------- fp16 tensor-core fused attention (bitmask, online softmax) ----------------
// 224 threads: 7 warps x exactly 2 strips. Paired pos LUT; mask as bits.
__global__ __launch_bounds__(224)
void attn_tc_kernel()
{
    extern __shared__ __half smh[];
    __half* Ksh  = smh;                          // [224][40] half
    __half* Vth  = Ksh + NKP*KS_STRH;            // [32][248] half (V^T)
    float2* poshd = (float2*)(Vth + 32*VT_STRH); // [1331] (pos[a], pos[a-1])
    short*  midv  = (short*)(poshd + M_POS);     // [216] pid3 LUT

    int bh = blockIdx.x;
    int b  = bh / HEADS, h = bh % HEADS;
    int g  = b & (NG_-1);
    int tid = threadIdx.x;
    int w = tid >> 5, lane = tid & 31;
    int grp = lane >> 2, tig = lane & 3;

    const __half* kvbh = g_kvh + (size_t)b*NTOK*(2*CH);
    for (int e = tid; e < NKP*16; e += 224) {
        int m = e >> 4, d = (e & 15)*2;
        uint32_t ku = 0u, vu = 0u;
        if (m < NTOK) {
            ku = *(const uint32_t*)&kvbh[(size_t)m*(2*CH) + h*32 + d];
            vu = *(const uint32_t*)&kvbh[(size_t)m*(2*CH) + CH + h*32 + d];
        }
        *(uint32_t*)&Ksh[m*KS_STRH + d] = ku;
        __half2 vh = *(__half2*)&vu;
        Vth[(d    )*VT_STRH + m] = vh.x;
        Vth[(d + 1)*VT_STRH + m] = vh.y;
    }
    for (int e = tid; e < M_POS; e += 224) {
        float cur = g_pos[h*M_POS + e];
        float prv = (e > 0) ? g_pos[h*M_POS + e - 1] : 0.f;
        poshd[e] = make_float2(cur, prv);
    }
    for (int e = tid; e < NTOK; e += 224)
        midv[e] = (short)((e/36)*121 + ((e/6)%6)*11 + (e%6));
    __syncthreads();

    const __half* qbh = g_qh + (size_t)b*NTOK*CH + h*32;
    __half* obh = g_atth + (size_t)b*NTOK*CH + h*32;
    const uint32_t* mbase = g_mbits + (size_t)g*NTOK*8;
    const float scale = 0.17677669529663687f;  // 32^-0.5

    for (int strip = w; strip < MT; strip += 7) {
        int n0 = strip*16;
        int ra = n0 + grp, rb = ra + 8;
        int ra_c = min(ra, NTOK-1), rb_c = min(rb, NTOK-1);

        // Q A-frags: direct half2 loads
        uint32_t aq[2][4];
        const __half* qa = qbh + (size_t)ra_c*CH;
        const __half* qB = qbh + (size_t)rb_c*CH;
        #pragma unroll
        for (int c = 0; c < 2; c++) {
            aq[c][0] = *(const uint32_t*)&qa[c*16 + 2*tig];
            aq[c][1] = *(const uint32_t*)&qB[c*16 + 2*tig];
            aq[c][2] = *(const uint32_t*)&qa[c*16 + 2*tig + 8];
            aq[c][3] = *(const uint32_t*)&qB[c*16 + 2*tig + 8];
        }

        // row bitmasks (7 words each, broadcast loads)
        uint32_t mba[7], mbb[7];
        {
            const uint32_t* ma = mbase + (size_t)ra_c*8;
            const uint32_t* mb = mbase + (size_t)rb_c*8;
            #pragma unroll
            for (int i = 0; i < 7; i++) { mba[i] = ma[i]; mbb[i] = mb[i]; }
        }

        int nida = midv[ra_c], nidb = midv[rb_c];

        float o[4][4];
        #pragma unroll
        for (int dt = 0; dt < 4; dt++)
            #pragma unroll
            for (int c = 0; c < 4; c++) o[dt][c] = 0.f;
        float sa = 0.f, sb = 0.f;

        #pragma unroll 2
        for (int kt = 0; kt < KT16; kt++) {
            // S tiles = Q K^T
            float s0c[4] = {0.f,0.f,0.f,0.f};
            float s1c[4] = {0.f,0.f,0.f,0.f};
            int key0 = kt*16 + grp;
            #pragma unroll
            for (int c = 0; c < 2; c++) {
                uint32_t b0 = *(const uint32_t*)&Ksh[(key0    )*KS_STRH + c*16 + 2*tig];
                uint32_t b1 = *(const uint32_t*)&Ksh[(key0    )*KS_STRH + c*16 + 2*tig + 8];
                uint32_t d0 = *(const uint32_t*)&Ksh[(key0 + 8)*KS_STRH + c*16 + 2*tig];
                uint32_t d1 = *(const uint32_t*)&Ksh[(key0 + 8)*KS_STRH + c*16 + 2*tig + 8];
                asm volatile(
                    "mma.sync.aligned.m16n8k16.row.col.f32.f16.f16.f32 "
                    "{%0,%1,%2,%3}, {%4,%5,%6,%7}, {%8,%9}, {%0,%1,%2,%3};"
                    : "+f"(s0c[0]), "+f"(s0c[1]), "+f"(s0c[2]), "+f"(s0c[3])
                    : "r"(aq[c][0]), "r"(aq[c][1]), "r"(aq[c][2]), "r"(aq[c][3]),
                      "r"(b0), "r"(b1));
                asm volatile(
                    "mma.sync.aligned.m16n8k16.row.col.f32.f16.f16.f32 "
                    "{%0,%1,%2,%3}, {%4,%5,%6,%7}, {%8,%9}, {%0,%1,%2,%3};"
                    : "+f"(s1c[0]), "+f"(s1c[1]), "+f"(s1c[2]), "+f"(s1c[3])
                    : "r"(aq[c][0]), "r"(aq[c][1]), "r"(aq[c][2]), "r"(aq[c][3]),
                      "r"(d0), "r"(d1));
            }

            // mask bits for this kt (compile-time word index under unroll)
            uint32_t wa = mba[kt >> 1] >> ((kt & 1)*16 + 2*tig);
            uint32_t wb = mbb[kt >> 1] >> ((kt & 1)*16 + 2*tig);

            // bias(paired LUT) + bitmask + exp, accumulate row sums, pack P frags
            uint32_t pa0, pa1, pa2, pa3;
            {
                int m0 = kt*16 + 2*tig;
                int mid0 = midv[m0];
                float2 Pa = poshd[nida - mid0 + 665];   // .x even m, .y odd m
                float2 Pb = poshd[nidb - mid0 + 665];
                float p00 = (wa & 1u)   ? 0.f : __expf(s0c[0]*scale + Pa.x);
                float p01 = (wa & 2u)   ? 0.f : __expf(s0c[1]*scale + Pa.y);
                float p02 = (wb & 1u)   ? 0.f : __expf(s0c[2]*scale + Pb.x);
                float p03 = (wb & 2u)   ? 0.f : __expf(s0c[3]*scale + Pb.y);
                sa += p00 + p01;
                sb += p02 + p03;
                pa0 = pack_h2(p00, p01);
                pa1 = pack_h2(p02, p03);
            }
            if (kt < KT16-1) {
                int m1 = kt*16 + 8 + 2*tig;
                int mid1 = midv[m1];
                float2 Pa = poshd[nida - mid1 + 665];
                float2 Pb = poshd[nidb - mid1 + 665];
                float p10 = (wa & 0x100u) ? 0.f : __expf(s1c[0]*scale + Pa.x);
                float p11 = (wa & 0x200u) ? 0.f : __expf(s1c[1]*scale + Pa.y);
                float p12 = (wb & 0x100u) ? 0.f : __expf(s1c[2]*scale + Pb.x);
                float p13 = (wb & 0x200u) ? 0.f : __expf(s1c[3]*scale + Pb.y);
                sa += p10 + p11;
                sb += p12 + p13;
                pa2 = pack_h2(p10, p11);
                pa3 = pack_h2(p12, p13);
            } else {
                pa2 = 0u; pa3 = 0u;
            }

            // O += P V
            #pragma unroll
            for (int dt = 0; dt < 4; dt++) {
                uint32_t b0 = *(const uint32_t*)&Vth[(dt*8 + grp)*VT_STRH + kt*16 + 2*tig];
                uint32_t b1 = *(const uint32_t*)&Vth[(dt*8 + grp)*VT_STRH + kt*16 + 2*tig + 8];
                asm volatile(
                    "mma.sync.aligned.m16n8k16.row.col.f32.f16.f16.f32 "
                    "{%0,%1,%2,%3}, {%4,%5,%6,%7}, {%8,%9}, {%0,%1,%2,%3};"
                    : "+f"(o[dt][0]), "+f"(o[dt][1]), "+f"(o[dt][2]), "+f"(o[dt][3])
                    : "r"(pa0), "r"(pa1), "r"(pa2), "r"(pa3),
                      "r"(b0), "r"(b1));
            }
        }

        sa += __shfl_xor_sync(0xffffffffu, sa, 1);
        sa += __shfl_xor_sync(0xffffffffu, sa, 2);
        sb += __shfl_xor_sync(0xffffffffu, sb, 1);
        sb += __shfl_xor_sync(0xffffffffu, sb, 2);
        float inva = 1.f / sa, invb = 1.f / sb;

        #pragma unroll
        for (int dt = 0; dt < 4; dt++) {
            int d = dt*8 + 2*tig;
            *(uint32_t*)&obh[(size_t)ra*CH + d] =
                pack_h2(o[dt][0]*inva, o[dt][1]*inva);
            if (rb < NTOK)
                *(uint32_t*)&obh[(size_t)rb*CH + d] =
                    pack_h2(o[dt][2]*invb, o[dt][3]*invb);
        }
    }
}

// ---------------- launch ----------------
extern "C" void kernel_launch(void* const* d_in, const int* in_sizes, int n_in,
                              void* d_out, int out_size)
{
    const float* x     = (const float*)d_in[0];
    const float* y     = (const float*)d_in[1];
    const float* mask  = (const float*)d_in[2];
    const float* Wqkv  = (const float*)d_in[3];
    const float* bqkv  = (const float*)d_in[4];
    const float* Wproj = (const float*)d_in[5];
    const float* bproj = (const float*)d_in[6];
    const float* ppw   = (const float*)d_in[7];
    const float* ppb   = (const float*)d_in[8];
    const float* g1    = (const float*)d_in[9];
    const float* be1   = (const float*)d_in[10];
    const float* w1    = (const float*)d_in[11];
    const float* b1    = (const float*)d_in[12];
    const float* g2    = (const float*)d_in[13];
    const float* be2   = (const float*)d_in[14];
    const float* w2    = (const float*)d_in[15];
    const float* b2    = (const float*)d_in[16];
    const float* g3    = (const float*)d_in[17];
    const float* be3   = (const float*)d_in[18];
    const float* w3    = (const float*)d_in[19];
    const float* b3    = (const float*)d_in[20];
    float* out = (float*)d_out;

    __half *qp, *kvp, *attp, *whp;
    cudaGetSymbolAddress((void**)&qp,   g_qh);
    cudaGetSymbolAddress((void**)&kvp,  g_kvh);
    cudaGetSymbolAddress((void**)&attp, g_atth);
    cudaGetSymbolAddress((void**)&whp,  g_wh);

    pos_mlp_kernel<<<(M_POS+255)/256, 256>>>(ppw, ppb, g1, be1, w1, b1,
                                             g2, be2, w2, b2, g3, be3, w3, b3);
    conv_w_kernel<<<(4*CH*CH/4 + 255)/256, 256>>>(Wqkv, Wproj);
    mask_bits_kernel<<<(NG_*NTOK*32 + 255)/256, 256>>>(mask);

    cudaFuncSetAttribute(gemm_f16_big<false,true>,
                         cudaFuncAttributeMaxDynamicSharedMemorySize, GSMEM);
    cudaFuncSetAttribute(gemm_f16_big<true,false>,
                         cudaFuncAttributeMaxDynamicSharedMemorySize, GSMEM);

    // Q = x @ Wq^T + bq  -> half
    gemm_f16_big<false,true><<<MROWS/128, 256, GSMEM>>>(x, whp, bqkv, qp, CH);
    // KV = y @ Wkv^T + bkv -> half
    gemm_f16_big<false,true><<<MROWS/128, 256, GSMEM>>>(y, whp + (size_t)CH*CH,
                                                        bqkv + CH, kvp, 2*CH);
    // fused attention (half in, half out; mask via bitmask)
    {
        size_t smem = (size_t)(NKP*KS_STRH + 32*VT_STRH)*2
                    + (size_t)M_POS*8 + (size_t)NTOK*2;
        cudaFuncSetAttribute(attn_tc_kernel, cudaFuncAttributeMaxDynamicSharedMemorySize, (int)smem);
        attn_tc_kernel<<<B_*HEADS, 224, smem>>>();
    }
    // out = att @ Wproj^T + bproj  (half A, float out)
    gemm_f16_big<true,false><<<MROWS/128, 256, GSMEM>>>(attp, whp + (size_t)3*CH*CH,
                                                        bproj, out, CH);
}